// round 8
// baseline (speedup 1.0000x reference)
#include <cuda_runtime.h>
#include <math.h>
#include <stdint.h>

// Problem dims (fixed)
#define NN_ 4096
#define DD_ 256
#define HH_ 4
#define DHH_ 256
#define QKVD_ 1024
#define OUTD_ 128

// ---------------- scratch (device globals) ------------------------------------
__device__ float g_h1[NN_ * DD_];
__device__ float g_t1[NN_ * DD_];
__device__ float g_h2[NN_ * DD_];
__device__ float g_q[NN_ * QKVD_];     // later reused as 4 per-head PV outputs
__device__ float g_k[NN_ * QKVD_];
__device__ float g_v[NN_ * QKVD_];
__device__ float g_s[(size_t)HH_ * NN_ * NN_];
__device__ float g_agg[NN_ * DD_];
__device__ float g_t2[NN_ * DD_];
__device__ float g_t3[NN_ * DD_];
__device__ float g_h4[NN_ * DD_];

__device__ __forceinline__ uint32_t f2tf32(float f) {
    uint32_t u;
    asm("cvt.rna.tf32.f32 %0, %1;" : "=r"(u) : "f"(f));
    return u;
}

__device__ __forceinline__ void mma_tf32(float* d, const uint32_t* a, const uint32_t* b) {
    asm volatile(
        "mma.sync.aligned.m16n8k8.row.col.f32.tf32.tf32.f32 "
        "{%0,%1,%2,%3}, {%4,%5,%6,%7}, {%8,%9}, {%0,%1,%2,%3};\n"
        : "+f"(d[0]), "+f"(d[1]), "+f"(d[2]), "+f"(d[3])
        : "r"(a[0]), "r"(a[1]), "r"(a[2]), "r"(a[3]), "r"(b[0]), "r"(b[1]));
}

__device__ __forceinline__ void cp_async16(void* smem_dst, const void* gmem_src) {
    uint32_t dst = (uint32_t)__cvta_generic_to_shared(smem_dst);
    asm volatile("cp.async.cg.shared.global [%0], [%1], 16;\n"
                 :: "r"(dst), "l"(gmem_src));
}

// ---------------- TF32 tensor-core GEMM, 4-stage cp.async pipeline -------------
// C = act(alpha*A@B(^T) + bias + res), A [M,K] row-major.
// 128 threads = 4 warps (2x2), warp tile WM x WN of m16n8k8 atoms, BK=16.
// smem holds raw fp32 tiles; tf32 rounding at fragment-load time.
// Layouts: As [m][k] pad 20, Bs(transB) [n][k] pad 20, Bs(K-major) [k][n] pad BN+8.
template <int BM, int BN, int WM, int WN, bool TRANSB, int ACT, bool HAS_RES>
__global__ void __launch_bounds__(128, 3) gemm_tc(
    const float* __restrict__ A, int lda, long sAb,
    const float* __restrict__ B, int ldb, long sBb,
    const float* __restrict__ bias,
    const float* __restrict__ res, int ldres,
    float* __restrict__ C, int ldc, long sCb,
    int K, float alpha)
{
    constexpr int BK = 16;
    constexpr int STAGES = 4;
    constexpr int AM = WM / 16;
    constexpr int AN = WN / 8;
    constexpr int PA  = BK + 4;                 // 20
    constexpr int PBT = BK + 4;                 // 20
    constexpr int PBN = BN + 8;
    constexpr int AW = BM * PA;                                // A stage words
    constexpr int BW = TRANSB ? (BN * PBT) : (BK * PBN);       // B stage words
    constexpr int NCA = BM * BK / (4 * 128);    // 16B chunks/thread for A
    constexpr int NCB = BN * BK / (4 * 128);    // same count either B layout

    const int batch = blockIdx.z;
    A += (long)batch * sAb;
    B += (long)batch * sBb;
    C += (long)batch * sCb;

    extern __shared__ float sm[];
    float* AsB = sm;                   // [STAGES][AW]
    float* BsB = sm + STAGES * AW;     // [STAGES][BW]

    const int t    = threadIdx.x;
    const int warp = t >> 5;
    const int lane = t & 31;
    const int g    = lane >> 2;
    const int tig  = lane & 3;
    const int wm0  = (warp >> 1) * WM;
    const int wn0  = (warp & 1) * WN;
    const int row0 = blockIdx.y * BM;
    const int col0 = blockIdx.x * BN;

    float d[AM][AN][4];
#pragma unroll
    for (int am = 0; am < AM; am++)
#pragma unroll
        for (int an = 0; an < AN; an++)
#pragma unroll
            for (int i = 0; i < 4; i++) d[am][an][i] = 0.f;

    // ---- async tile issue (tile index -> stage buffer) ----
    auto issue_tile = [&](int tile, int buf) {
        const int k0 = tile * BK;
        float* Ad = AsB + buf * AW;
        float* Bd = BsB + buf * BW;
#pragma unroll
        for (int i = 0; i < NCA; i++) {
            int c   = t + i * 128;
            int r   = c >> 2;              // 0..BM-1
            int col = (c & 3) * 4;         // 0,4,8,12
            cp_async16(Ad + r * PA + col, &A[(long)(row0 + r) * lda + k0 + col]);
        }
        if (TRANSB) {
#pragma unroll
            for (int i = 0; i < NCB; i++) {
                int c   = t + i * 128;
                int r   = c >> 2;          // n: 0..BN-1
                int col = (c & 3) * 4;     // k
                cp_async16(Bd + r * PBT + col, &B[(long)(col0 + r) * ldb + k0 + col]);
            }
        } else {
#pragma unroll
            for (int i = 0; i < NCB; i++) {
                int c   = t + i * 128;
                int r   = c / (BN / 4);            // k: 0..15
                int col = (c % (BN / 4)) * 4;      // n
                cp_async16(Bd + r * PBN + col, &B[(long)(k0 + r) * ldb + col0 + col]);
            }
        }
    };

    const int nit = K / BK;

    // ---- prologue: fill STAGES-1 buffers ----
#pragma unroll
    for (int s = 0; s < STAGES - 1; s++) {
        issue_tile(s, s);
        asm volatile("cp.async.commit_group;\n" ::);
    }
    asm volatile("cp.async.wait_group %0;\n" :: "n"(STAGES - 2));
    __syncthreads();

    for (int it = 0; it < nit; it++) {
        const int buf = it % STAGES;
        const int pf  = it + STAGES - 1;
        if (pf < nit) issue_tile(pf, pf % STAGES);
        asm volatile("cp.async.commit_group;\n" ::);

        const float* Ab = AsB + buf * AW;
        const float* Bb = BsB + buf * BW;

#pragma unroll
        for (int ks = 0; ks < 2; ks++) {
            const int kk = ks * 8;
            uint32_t a[AM][4], b[AN][2];
#pragma unroll
            for (int am = 0; am < AM; am++) {
                const int mr = wm0 + am * 16 + g;
                a[am][0] = f2tf32(Ab[mr * PA + kk + tig]);
                a[am][1] = f2tf32(Ab[(mr + 8) * PA + kk + tig]);
                a[am][2] = f2tf32(Ab[mr * PA + kk + tig + 4]);
                a[am][3] = f2tf32(Ab[(mr + 8) * PA + kk + tig + 4]);
            }
#pragma unroll
            for (int an = 0; an < AN; an++) {
                const int nc = wn0 + an * 8 + g;
                if (TRANSB) {
                    b[an][0] = f2tf32(Bb[nc * PBT + kk + tig]);
                    b[an][1] = f2tf32(Bb[nc * PBT + kk + tig + 4]);
                } else {
                    b[an][0] = f2tf32(Bb[(kk + tig) * PBN + nc]);
                    b[an][1] = f2tf32(Bb[(kk + tig + 4) * PBN + nc]);
                }
            }
#pragma unroll
            for (int am = 0; am < AM; am++)
#pragma unroll
                for (int an = 0; an < AN; an++)
                    mma_tf32(d[am][an], a[am], b[an]);
        }

        asm volatile("cp.async.wait_group %0;\n" :: "n"(STAGES - 2));
        __syncthreads();
    }

    // ---- epilogue ----
#pragma unroll
    for (int am = 0; am < AM; am++) {
#pragma unroll
        for (int an = 0; an < AN; an++) {
            const int c0 = col0 + wn0 + an * 8 + tig * 2;
#pragma unroll
            for (int half = 0; half < 2; half++) {
                const int r = row0 + wm0 + am * 16 + g + half * 8;
#pragma unroll
                for (int j = 0; j < 2; j++) {
                    const int c = c0 + j;
                    float v = alpha * d[am][an][half * 2 + j];
                    if (bias) v += bias[c];
                    if (HAS_RES) v += res[(long)r * ldres + c];
                    if (ACT == 1) v = (v > 0.f) ? v : expm1f(v);   // ELU
                    if (ACT == 2) v = fmaxf(v, 0.f);               // ReLU
                    C[(long)r * ldc + c] = v;
                }
            }
        }
    }
}

// dynamic smem bytes for a given instantiation
template <int BM, int BN, bool TRANSB>
constexpr int smem_bytes() {
    constexpr int BK = 16, STAGES = 4;
    constexpr int AW = BM * (BK + 4);
    constexpr int BW = TRANSB ? (BN * (BK + 4)) : (BK * (BN + 8));
    return STAGES * (AW + BW) * 4;
}

// ---------------- block reduce (256 threads) -----------------------------------
__device__ __forceinline__ float block_reduce_256(float v, bool do_max)
{
    __shared__ float sm[8];
#pragma unroll
    for (int o = 16; o > 0; o >>= 1) {
        float u = __shfl_xor_sync(0xffffffffu, v, o);
        v = do_max ? fmaxf(v, u) : (v + u);
    }
    const int warp = threadIdx.x >> 5;
    if ((threadIdx.x & 31) == 0) sm[warp] = v;
    __syncthreads();
    float r = sm[0];
#pragma unroll
    for (int i = 1; i < 8; i++) r = do_max ? fmaxf(r, sm[i]) : (r + sm[i]);
    __syncthreads();
    return r;
}

// ---------------- softmax over rows of 4096 (in place) -------------------------
__global__ void __launch_bounds__(256) softmax_k(float* __restrict__ S)
{
    const long row = blockIdx.x;
    float* p = S + row * (long)NN_;
    const int t = threadIdx.x;

    float v[16];
    float m = -1e30f;
#pragma unroll
    for (int i = 0; i < 16; i++) { v[i] = p[i * 256 + t]; m = fmaxf(m, v[i]); }
    m = block_reduce_256(m, true);

    float s = 0.f;
#pragma unroll
    for (int i = 0; i < 16; i++) { v[i] = __expf(v[i] - m); s += v[i]; }
    s = block_reduce_256(s, false);

    const float inv = 1.f / s;
#pragma unroll
    for (int i = 0; i < 16; i++) p[i * 256 + t] = v[i] * inv;
}

// ---------------- LayerNorm over rows of 256 -----------------------------------
__global__ void __launch_bounds__(256) ln_k(
    const float* __restrict__ X, const float* __restrict__ g,
    const float* __restrict__ b, float* __restrict__ Y)
{
    const int row = blockIdx.x;
    const int t = threadIdx.x;
    const float x = X[row * DD_ + t];
    const float mean = block_reduce_256(x, false) * (1.f / 256.f);
    const float d = x - mean;
    const float var = block_reduce_256(d * d, false) * (1.f / 256.f);
    Y[row * DD_ + t] = d * rsqrtf(var + 1e-5f) * g[t] + b[t];
}

// ---- LN of (skip + sum of 4 per-head PV outputs), heads pre-scaled by 0.25 ----
__global__ void __launch_bounds__(256) ln_agg_k(
    const float* __restrict__ skip, const float* __restrict__ ph,
    const float* __restrict__ g, const float* __restrict__ b,
    float* __restrict__ Y)
{
    const int row = blockIdx.x;
    const int t = threadIdx.x;
    const long i = (long)row * DD_ + t;
    const long S = (long)NN_ * DD_;
    const float x = skip[i] + ph[i] + ph[i + S] + ph[i + 2 * S] + ph[i + 3 * S];
    const float mean = block_reduce_256(x, false) * (1.f / 256.f);
    const float d = x - mean;
    const float var = block_reduce_256(d * d, false) * (1.f / 256.f);
    Y[row * DD_ + t] = d * rsqrtf(var + 1e-5f) * g[t] + b[t];
}

// ---------------- launch --------------------------------------------------------
extern "C" void kernel_launch(void* const* d_in, const int* in_sizes, int n_in,
                              void* d_out, int out_size)
{
    const float* x      = (const float*)d_in[0];
    const float* w_in   = (const float*)d_in[1];
    const float* b_in   = (const float*)d_in[2];
    const float* w_m1   = (const float*)d_in[3];
    const float* b_m1   = (const float*)d_in[4];
    const float* g_m1   = (const float*)d_in[5];
    const float* be_m1  = (const float*)d_in[6];
    const float* wq     = (const float*)d_in[7];
    const float* bq     = (const float*)d_in[8];
    const float* wk     = (const float*)d_in[9];
    const float* bk     = (const float*)d_in[10];
    const float* wv     = (const float*)d_in[11];
    const float* bv     = (const float*)d_in[12];
    const float* wskip  = (const float*)d_in[13];
    const float* bskip  = (const float*)d_in[14];
    const float* g_n1   = (const float*)d_in[15];
    const float* be_n1  = (const float*)d_in[16];
    const float* w_m2   = (const float*)d_in[17];
    const float* b_m2   = (const float*)d_in[18];
    const float* g_m2   = (const float*)d_in[19];
    const float* be_m2  = (const float*)d_in[20];
    const float* w_mean = (const float*)d_in[21];
    const float* b_mean = (const float*)d_in[22];
    float* out = (float*)d_out;

    float *h1, *t1, *h2, *q, *k, *v, *s, *agg, *t2, *t3, *h4;
    cudaGetSymbolAddress((void**)&h1,  g_h1);
    cudaGetSymbolAddress((void**)&t1,  g_t1);
    cudaGetSymbolAddress((void**)&h2,  g_h2);
    cudaGetSymbolAddress((void**)&q,   g_q);
    cudaGetSymbolAddress((void**)&k,   g_k);
    cudaGetSymbolAddress((void**)&v,   g_v);
    cudaGetSymbolAddress((void**)&s,   g_s);
    cudaGetSymbolAddress((void**)&agg, g_agg);
    cudaGetSymbolAddress((void**)&t2,  g_t2);
    cudaGetSymbolAddress((void**)&t3,  g_t3);
    cudaGetSymbolAddress((void**)&h4,  g_h4);

    // opt-in to >48KB dynamic smem (host-side, capture-time only)
    constexpr int SM_SQ   = smem_bytes<64, 64, false>();
    constexpr int SM_BIG  = smem_bytes<128, 64, false>();
    constexpr int SM_BIGT = smem_bytes<128, 64, true>();
    cudaFuncSetAttribute(gemm_tc<64, 64, 32, 32, false, 1, true>,
        cudaFuncAttributeMaxDynamicSharedMemorySize, SM_SQ);
    cudaFuncSetAttribute(gemm_tc<64, 64, 32, 32, false, 2, true>,
        cudaFuncAttributeMaxDynamicSharedMemorySize, SM_SQ);
    cudaFuncSetAttribute(gemm_tc<64, 64, 32, 32, false, 0, false>,
        cudaFuncAttributeMaxDynamicSharedMemorySize, SM_SQ);
    cudaFuncSetAttribute(gemm_tc<128, 64, 64, 32, false, 0, false>,
        cudaFuncAttributeMaxDynamicSharedMemorySize, SM_BIG);
    cudaFuncSetAttribute(gemm_tc<128, 64, 64, 32, true, 0, false>,
        cudaFuncAttributeMaxDynamicSharedMemorySize, SM_BIGT);

    const dim3 blk(128);
    const dim3 blk256(256);

    // small config: 64x64 tile, warp 32x32
    const dim3 gSq(DD_ / 64, NN_ / 64);          // (4, 64)
    const dim3 gOut(OUTD_ / 64, NN_ / 64);       // (2, 64)
    // big config: 128x64 CTA tile, warp 64x32
    const dim3 gQkv(QKVD_ / 64, NN_ / 128);          // (16, 32)
    const dim3 gScore(NN_ / 64, NN_ / 128, HH_);     // (64, 32, 4)
    const dim3 gPV(DHH_ / 64, NN_ / 128, HH_);       // (4, 32, 4)

    // 1) h1 = elu(x @ w_in + b_in + x)
    gemm_tc<64, 64, 32, 32, false, 1, true><<<gSq, blk, SM_SQ>>>(x, DD_, 0,
        w_in, DD_, 0, b_in, x, DD_, h1, DD_, 0, DD_, 1.f);

    // 2) t1 = relu(h1 @ w_m1 + b_m1 + h1);  h2 = LN(t1)
    gemm_tc<64, 64, 32, 32, false, 2, true><<<gSq, blk, SM_SQ>>>(h1, DD_, 0,
        w_m1, DD_, 0, b_m1, h1, DD_, t1, DD_, 0, DD_, 1.f);
    ln_k<<<NN_, blk256>>>(t1, g_m1, be_m1, h2);

    // 3) q/k/v projections
    gemm_tc<128, 64, 64, 32, false, 0, false><<<gQkv, blk, SM_BIG>>>(h2, DD_, 0,
        wq, QKVD_, 0, bq, nullptr, 0, q, QKVD_, 0, DD_, 1.f);
    gemm_tc<128, 64, 64, 32, false, 0, false><<<gQkv, blk, SM_BIG>>>(h2, DD_, 0,
        wk, QKVD_, 0, bk, nullptr, 0, k, QKVD_, 0, DD_, 1.f);
    gemm_tc<128, 64, 64, 32, false, 0, false><<<gQkv, blk, SM_BIG>>>(h2, DD_, 0,
        wv, QKVD_, 0, bv, nullptr, 0, v, QKVD_, 0, DD_, 1.f);

    // 4) scores: s[h] = (1/16) * Q_h @ K_h^T
    gemm_tc<128, 64, 64, 32, true, 0, false><<<gScore, blk, SM_BIGT>>>(
        q, QKVD_, DHH_, k, QKVD_, DHH_, nullptr, nullptr, 0,
        s, NN_, (long)NN_ * NN_, DHH_, 1.f / 16.f);

    // 5) softmax over source nodes
    softmax_k<<<HH_ * NN_, blk256>>>(s);

    // 6) agg = h2 @ wskip + bskip
    gemm_tc<64, 64, 32, 32, false, 0, false><<<gSq, blk, SM_SQ>>>(h2, DD_, 0,
        wskip, DD_, 0, bskip, nullptr, 0, agg, DD_, 0, DD_, 1.f);

    // 7) per-head PV (alpha=0.25), batched over heads; outputs into q's memory
    gemm_tc<128, 64, 64, 32, false, 0, false><<<gPV, blk, SM_BIG>>>(
        s, NN_, (long)NN_ * NN_,
        v, QKVD_, DHH_,
        nullptr, nullptr, 0,
        q, DD_, (long)NN_ * DD_, NN_, 0.25f);

    // 8) t2 = LN(agg + sum_h ph)
    ln_agg_k<<<NN_, blk256>>>(agg, q, g_n1, be_n1, t2);

    // 9) t3 = relu(t2 @ w_m2 + b_m2 + t2);  h4 = LN(t3)
    gemm_tc<64, 64, 32, 32, false, 2, true><<<gSq, blk, SM_SQ>>>(t2, DD_, 0,
        w_m2, DD_, 0, b_m2, t2, DD_, t3, DD_, 0, DD_, 1.f);
    ln_k<<<NN_, blk256>>>(t3, g_m2, be_m2, h4);

    // 10) out = h4 @ w_mean + b_mean
    gemm_tc<64, 64, 32, 32, false, 0, false><<<gOut, blk, SM_SQ>>>(h4, DD_, 0,
        w_mean, OUTD_, 0, b_mean, nullptr, 0, out, OUTD_, 0, DD_, 1.f);
}

// round 11
// speedup vs baseline: 1.1950x; 1.1950x over previous
#include <cuda_runtime.h>
#include <cuda_fp16.h>
#include <math.h>
#include <stdint.h>

// Problem dims (fixed)
#define NN_ 4096
#define DD_ 256
#define HH_ 4
#define DHH_ 256
#define QKVD_ 1024
#define OUTD_ 128

// ---------------- scratch (device globals) ------------------------------------
__device__ float g_h1[NN_ * DD_];
__device__ float g_t1[NN_ * DD_];
__device__ float g_h2[NN_ * DD_];
__device__ __align__(16) __half g_h2h[NN_ * DD_];
__device__ __align__(16) __half g_wqT[QKVD_ * DD_];   // [n][k] transposed weights
__device__ __align__(16) __half g_wkT[QKVD_ * DD_];
__device__ __align__(16) __half g_wvT[QKVD_ * DD_];
__device__ __align__(16) __half g_qh[NN_ * QKVD_];    // [n][h*256+d]
__device__ __align__(16) __half g_kh[NN_ * QKVD_];
__device__ __align__(16) __half g_vt[QKVD_ * NN_];    // [h*256+d][m]  (V transposed)
__device__ float g_s[(size_t)HH_ * NN_ * NN_];        // f32 scores (256 MiB)
__device__ __align__(16) __half g_p[(size_t)HH_ * NN_ * NN_];  // f16 probs (128 MiB)
__device__ float g_ph[NN_ * QKVD_];                   // per-head PV outputs f32 [h][n][256]
__device__ float g_agg[NN_ * DD_];
__device__ float g_t2[NN_ * DD_];
__device__ float g_t3[NN_ * DD_];
__device__ float g_h4[NN_ * DD_];

__device__ __forceinline__ uint32_t f2tf32(float f) {
    uint32_t u;
    asm("cvt.rna.tf32.f32 %0, %1;" : "=r"(u) : "f"(f));
    return u;
}

__device__ __forceinline__ void mma_tf32(float* d, const uint32_t* a, const uint32_t* b) {
    asm volatile(
        "mma.sync.aligned.m16n8k8.row.col.f32.tf32.tf32.f32 "
        "{%0,%1,%2,%3}, {%4,%5,%6,%7}, {%8,%9}, {%0,%1,%2,%3};\n"
        : "+f"(d[0]), "+f"(d[1]), "+f"(d[2]), "+f"(d[3])
        : "r"(a[0]), "r"(a[1]), "r"(a[2]), "r"(a[3]), "r"(b[0]), "r"(b[1]));
}

__device__ __forceinline__ void mma_f16(float* d, const uint32_t* a, const uint32_t* b) {
    asm volatile(
        "mma.sync.aligned.m16n8k16.row.col.f32.f16.f16.f32 "
        "{%0,%1,%2,%3}, {%4,%5,%6,%7}, {%8,%9}, {%0,%1,%2,%3};\n"
        : "+f"(d[0]), "+f"(d[1]), "+f"(d[2]), "+f"(d[3])
        : "r"(a[0]), "r"(a[1]), "r"(a[2]), "r"(a[3]), "r"(b[0]), "r"(b[1]));
}

__device__ __forceinline__ void cp_async16(void* smem_dst, const void* gmem_src) {
    uint32_t dst = (uint32_t)__cvta_generic_to_shared(smem_dst);
    asm volatile("cp.async.cg.shared.global [%0], [%1], 16;\n"
                 :: "r"(dst), "l"(gmem_src));
}

// ================= FP16 tensor-core GEMM (heavy ops) ===========================
// C = alpha * A @ B^T (+bias), fp32 accumulate.
// A [M][K] f16 row-major (lda elems); B [N][K] f16 row-major (ldb elems).
// CTA 128x64, 4 warps (2x2), warp tile 64x32 of m16n8k16 atoms, BK=32, 4 stages.
// smem: [rows][16 words], XOR swizzle cw ^= ((r>>1)&3)<<2 -> conflict-free.
// OUTM: 0 = f32 C[m][n]; 1 = f16 C[m][n] (+bias); 2 = f16 C[c][m] (+bias, transposed)
template <int OUTM>
__global__ void __launch_bounds__(128, 3) gemm_f16(
    const __half* __restrict__ A, int lda, long sAb,
    const __half* __restrict__ B, int ldb, long sBb,
    const float* __restrict__ bias,
    void* __restrict__ Cv, int ldc, long sCb,
    int K, float alpha)
{
    constexpr int BM = 128, BN = 64, BK = 32, STAGES = 4;
    constexpr int AM = 4, AN = 4;          // warp tile 64x32
    constexpr int AWW = BM * 16;           // A stage words
    constexpr int BWW = BN * 16;

    const int batch = blockIdx.z;
    A += batch * sAb;
    B += batch * sBb;

    extern __shared__ uint32_t smw[];
    uint32_t* Aw = smw;                    // [STAGES][AWW]
    uint32_t* Bw = smw + STAGES * AWW;     // [STAGES][BWW]

    const int t    = threadIdx.x;
    const int warp = t >> 5;
    const int lane = t & 31;
    const int g    = lane >> 2;
    const int tig  = lane & 3;
    const int wm0  = (warp >> 1) * 64;
    const int wn0  = (warp & 1) * 32;
    const int row0 = blockIdx.y * BM;
    const int col0 = blockIdx.x * BN;

    float d[AM][AN][4];
#pragma unroll
    for (int am = 0; am < AM; am++)
#pragma unroll
        for (int an = 0; an < AN; an++)
#pragma unroll
            for (int i = 0; i < 4; i++) d[am][an][i] = 0.f;

    auto issue = [&](int tile, int buf) {
        const int k0 = tile * BK;
        uint32_t* Ad = Aw + buf * AWW;
        uint32_t* Bd = Bw + buf * BWW;
#pragma unroll
        for (int i = 0; i < 4; i++) {          // 512 A chunks (16B each)
            int c  = t + i * 128;
            int r  = c >> 2;                   // 0..127
            int wb = (c & 3) * 4;              // word block 0,4,8,12
            cp_async16(Ad + r * 16 + (wb ^ (((r >> 1) & 3) << 2)),
                       A + (long)(row0 + r) * lda + k0 + 2 * wb);
        }
#pragma unroll
        for (int i = 0; i < 2; i++) {          // 256 B chunks
            int c  = t + i * 128;
            int r  = c >> 2;                   // 0..63
            int wb = (c & 3) * 4;
            cp_async16(Bd + r * 16 + (wb ^ (((r >> 1) & 3) << 2)),
                       B + (long)(col0 + r) * ldb + k0 + 2 * wb);
        }
    };

    const int nit = K / BK;

#pragma unroll
    for (int s = 0; s < STAGES - 1; s++) {
        issue(s, s);
        asm volatile("cp.async.commit_group;\n" ::);
    }
    asm volatile("cp.async.wait_group %0;\n" :: "n"(STAGES - 2));
    __syncthreads();

    const int swz = ((g >> 1) & 3) << 2;       // same for rows r and r+8

    for (int it = 0; it < nit; it++) {
        const int buf = it % STAGES;
        const int pf  = it + STAGES - 1;
        if (pf < nit) issue(pf, pf % STAGES);
        asm volatile("cp.async.commit_group;\n" ::);

        const uint32_t* Ab = Aw + buf * AWW;
        const uint32_t* Bb = Bw + buf * BWW;

#pragma unroll
        for (int ks = 0; ks < 2; ks++) {       // two k16 steps per BK=32
            const int kw = ks * 8;
            const int w0 = (kw + tig) ^ swz;
            const int w1 = (kw + tig + 4) ^ swz;
            uint32_t a[AM][4], b[AN][2];
#pragma unroll
            for (int am = 0; am < AM; am++) {
                const int mr = wm0 + am * 16 + g;
                const uint32_t* R0 = Ab + mr * 16;
                const uint32_t* R1 = Ab + (mr + 8) * 16;
                a[am][0] = R0[w0];
                a[am][1] = R1[w0];
                a[am][2] = R0[w1];
                a[am][3] = R1[w1];
            }
#pragma unroll
            for (int an = 0; an < AN; an++) {
                const int nc = wn0 + an * 8 + g;
                b[an][0] = Bb[nc * 16 + w0];
                b[an][1] = Bb[nc * 16 + w1];
            }
#pragma unroll
            for (int am = 0; am < AM; am++)
#pragma unroll
                for (int an = 0; an < AN; an++)
                    mma_f16(d[am][an], a[am], b[an]);
        }

        asm volatile("cp.async.wait_group %0;\n" :: "n"(STAGES - 2));
        __syncthreads();
    }

    // ---- epilogue ----
#pragma unroll
    for (int am = 0; am < AM; am++) {
#pragma unroll
        for (int an = 0; an < AN; an++) {
            const int c0 = col0 + wn0 + an * 8 + tig * 2;
#pragma unroll
            for (int half = 0; half < 2; half++) {
                const int r = row0 + wm0 + am * 16 + g + half * 8;
#pragma unroll
                for (int j = 0; j < 2; j++) {
                    const int c = c0 + j;
                    float v = alpha * d[am][an][half * 2 + j];
                    if (OUTM == 0) {
                        ((float*)Cv)[batch * sCb + (long)r * ldc + c] = v;
                    } else if (OUTM == 1) {
                        v += bias[c];
                        ((__half*)Cv)[batch * sCb + (long)r * ldc + c] = __float2half(v);
                    } else {
                        v += bias[c];
                        ((__half*)Cv)[batch * sCb + (long)c * ldc + r] = __float2half(v);
                    }
                }
            }
        }
    }
}

// ================= TF32 GEMM (small square ops; proven path) ===================
template <int BM, int BN, int WM, int WN, bool TRANSB, int ACT, bool HAS_RES>
__global__ void __launch_bounds__(128, 3) gemm_tc(
    const float* __restrict__ A, int lda, long sAb,
    const float* __restrict__ B, int ldb, long sBb,
    const float* __restrict__ bias,
    const float* __restrict__ res, int ldres,
    float* __restrict__ C, int ldc, long sCb,
    int K, float alpha)
{
    constexpr int BK = 16;
    constexpr int STAGES = 4;
    constexpr int AM = WM / 16;
    constexpr int AN = WN / 8;
    constexpr int PA  = BK + 4;
    constexpr int PBT = BK + 4;
    constexpr int PBN = BN + 8;
    constexpr int AW = BM * PA;
    constexpr int BW = TRANSB ? (BN * PBT) : (BK * PBN);
    constexpr int NCA = BM * BK / (4 * 128);
    constexpr int NCB = BN * BK / (4 * 128);

    const int batch = blockIdx.z;
    A += (long)batch * sAb;
    B += (long)batch * sBb;
    C += (long)batch * sCb;

    extern __shared__ float sm[];
    float* AsB = sm;
    float* BsB = sm + STAGES * AW;

    const int t    = threadIdx.x;
    const int warp = t >> 5;
    const int lane = t & 31;
    const int g    = lane >> 2;
    const int tig  = lane & 3;
    const int wm0  = (warp >> 1) * WM;
    const int wn0  = (warp & 1) * WN;
    const int row0 = blockIdx.y * BM;
    const int col0 = blockIdx.x * BN;

    float d[AM][AN][4];
#pragma unroll
    for (int am = 0; am < AM; am++)
#pragma unroll
        for (int an = 0; an < AN; an++)
#pragma unroll
            for (int i = 0; i < 4; i++) d[am][an][i] = 0.f;

    auto issue_tile = [&](int tile, int buf) {
        const int k0 = tile * BK;
        float* Ad = AsB + buf * AW;
        float* Bd = BsB + buf * BW;
#pragma unroll
        for (int i = 0; i < NCA; i++) {
            int c   = t + i * 128;
            int r   = c >> 2;
            int col = (c & 3) * 4;
            cp_async16(Ad + r * PA + col, &A[(long)(row0 + r) * lda + k0 + col]);
        }
        if (TRANSB) {
#pragma unroll
            for (int i = 0; i < NCB; i++) {
                int c   = t + i * 128;
                int r   = c >> 2;
                int col = (c & 3) * 4;
                cp_async16(Bd + r * PBT + col, &B[(long)(col0 + r) * ldb + k0 + col]);
            }
        } else {
#pragma unroll
            for (int i = 0; i < NCB; i++) {
                int c   = t + i * 128;
                int r   = c / (BN / 4);
                int col = (c % (BN / 4)) * 4;
                cp_async16(Bd + r * PBN + col, &B[(long)(k0 + r) * ldb + col0 + col]);
            }
        }
    };

    const int nit = K / BK;

#pragma unroll
    for (int s = 0; s < STAGES - 1; s++) {
        issue_tile(s, s);
        asm volatile("cp.async.commit_group;\n" ::);
    }
    asm volatile("cp.async.wait_group %0;\n" :: "n"(STAGES - 2));
    __syncthreads();

    for (int it = 0; it < nit; it++) {
        const int buf = it % STAGES;
        const int pf  = it + STAGES - 1;
        if (pf < nit) issue_tile(pf, pf % STAGES);
        asm volatile("cp.async.commit_group;\n" ::);

        const float* Ab = AsB + buf * AW;
        const float* Bb = BsB + buf * BW;

#pragma unroll
        for (int ks = 0; ks < 2; ks++) {
            const int kk = ks * 8;
            uint32_t a[AM][4], b[AN][2];
#pragma unroll
            for (int am = 0; am < AM; am++) {
                const int mr = wm0 + am * 16 + g;
                a[am][0] = f2tf32(Ab[mr * PA + kk + tig]);
                a[am][1] = f2tf32(Ab[(mr + 8) * PA + kk + tig]);
                a[am][2] = f2tf32(Ab[mr * PA + kk + tig + 4]);
                a[am][3] = f2tf32(Ab[(mr + 8) * PA + kk + tig + 4]);
            }
#pragma unroll
            for (int an = 0; an < AN; an++) {
                const int nc = wn0 + an * 8 + g;
                if (TRANSB) {
                    b[an][0] = f2tf32(Bb[nc * PBT + kk + tig]);
                    b[an][1] = f2tf32(Bb[nc * PBT + kk + tig + 4]);
                } else {
                    b[an][0] = f2tf32(Bb[(kk + tig) * PBN + nc]);
                    b[an][1] = f2tf32(Bb[(kk + tig + 4) * PBN + nc]);
                }
            }
#pragma unroll
            for (int am = 0; am < AM; am++)
#pragma unroll
                for (int an = 0; an < AN; an++)
                    mma_tf32(d[am][an], a[am], b[an]);
        }

        asm volatile("cp.async.wait_group %0;\n" :: "n"(STAGES - 2));
        __syncthreads();
    }

#pragma unroll
    for (int am = 0; am < AM; am++) {
#pragma unroll
        for (int an = 0; an < AN; an++) {
            const int c0 = col0 + wn0 + an * 8 + tig * 2;
#pragma unroll
            for (int half = 0; half < 2; half++) {
                const int r = row0 + wm0 + am * 16 + g + half * 8;
#pragma unroll
                for (int j = 0; j < 2; j++) {
                    const int c = c0 + j;
                    float v = alpha * d[am][an][half * 2 + j];
                    if (bias) v += bias[c];
                    if (HAS_RES) v += res[(long)r * ldres + c];
                    if (ACT == 1) v = (v > 0.f) ? v : expm1f(v);
                    if (ACT == 2) v = fmaxf(v, 0.f);
                    C[(long)r * ldc + c] = v;
                }
            }
        }
    }
}

template <int BM, int BN, bool TRANSB>
constexpr int smem_bytes() {
    constexpr int BK = 16, STAGES = 4;
    constexpr int AW = BM * (BK + 4);
    constexpr int BW = TRANSB ? (BN * (BK + 4)) : (BK * (BN + 8));
    return STAGES * (AW + BW) * 4;
}
constexpr int SMEM_F16 = 4 * (128 * 16 + 64 * 16) * 4;   // 49152 B

// ---------------- weight transpose+convert: wT[n][k] = f16(w[k][n]) ------------
__global__ void convT_k(const float* __restrict__ w, __half* __restrict__ wt, int Kin, int Nout)
{
    int i = blockIdx.x * 256 + threadIdx.x;      // over Nout*Kin
    int n = i / Kin, k = i - n * Kin;
    wt[i] = __float2half(w[(long)k * Nout + n]);
}

// ---------------- block reduce (256 threads) -----------------------------------
__device__ __forceinline__ float block_reduce_256(float v, bool do_max)
{
    __shared__ float sm[8];
#pragma unroll
    for (int o = 16; o > 0; o >>= 1) {
        float u = __shfl_xor_sync(0xffffffffu, v, o);
        v = do_max ? fmaxf(v, u) : (v + u);
    }
    const int warp = threadIdx.x >> 5;
    if ((threadIdx.x & 31) == 0) sm[warp] = v;
    __syncthreads();
    float r = sm[0];
#pragma unroll
    for (int i = 1; i < 8; i++) r = do_max ? fmaxf(r, sm[i]) : (r + sm[i]);
    __syncthreads();
    return r;
}

// ---------------- softmax over rows of 4096: f32 in -> f16 probs out -----------
__global__ void __launch_bounds__(256) softmax_k(const float* __restrict__ S,
                                                 __half* __restrict__ P)
{
    const long row = blockIdx.x;
    const float* p = S + row * (long)NN_;
    __half* o = P + row * (long)NN_;
    const int t = threadIdx.x;

    float v[16];
    float m = -1e30f;
#pragma unroll
    for (int i = 0; i < 16; i++) { v[i] = p[i * 256 + t]; m = fmaxf(m, v[i]); }
    m = block_reduce_256(m, true);

    float s = 0.f;
#pragma unroll
    for (int i = 0; i < 16; i++) { v[i] = __expf(v[i] - m); s += v[i]; }
    s = block_reduce_256(s, false);

    const float inv = 1.f / s;
#pragma unroll
    for (int i = 0; i < 16; i++) o[i * 256 + t] = __float2half(v[i] * inv);
}

// ---------------- LayerNorm over rows of 256 (optional f16 secondary out) ------
__global__ void __launch_bounds__(256) ln_k(
    const float* __restrict__ X, const float* __restrict__ g,
    const float* __restrict__ b, float* __restrict__ Y, __half* __restrict__ Y16)
{
    const int row = blockIdx.x;
    const int t = threadIdx.x;
    const float x = X[row * DD_ + t];
    const float mean = block_reduce_256(x, false) * (1.f / 256.f);
    const float d = x - mean;
    const float var = block_reduce_256(d * d, false) * (1.f / 256.f);
    const float y = d * rsqrtf(var + 1e-5f) * g[t] + b[t];
    Y[row * DD_ + t] = y;
    if (Y16) Y16[row * DD_ + t] = __float2half(y);
}

// ---- LN of (skip + sum of 4 per-head PV outputs), heads pre-scaled by 0.25 ----
__global__ void __launch_bounds__(256) ln_agg_k(
    const float* __restrict__ skip, const float* __restrict__ ph,
    const float* __restrict__ g, const float* __restrict__ b,
    float* __restrict__ Y)
{
    const int row = blockIdx.x;
    const int t = threadIdx.x;
    const long i = (long)row * DD_ + t;
    const long S = (long)NN_ * DD_;
    const float x = skip[i] + ph[i] + ph[i + S] + ph[i + 2 * S] + ph[i + 3 * S];
    const float mean = block_reduce_256(x, false) * (1.f / 256.f);
    const float d = x - mean;
    const float var = block_reduce_256(d * d, false) * (1.f / 256.f);
    Y[row * DD_ + t] = d * rsqrtf(var + 1e-5f) * g[t] + b[t];
}

// ---------------- launch --------------------------------------------------------
extern "C" void kernel_launch(void* const* d_in, const int* in_sizes, int n_in,
                              void* d_out, int out_size)
{
    const float* x      = (const float*)d_in[0];
    const float* w_in   = (const float*)d_in[1];
    const float* b_in   = (const float*)d_in[2];
    const float* w_m1   = (const float*)d_in[3];
    const float* b_m1   = (const float*)d_in[4];
    const float* g_m1   = (const float*)d_in[5];
    const float* be_m1  = (const float*)d_in[6];
    const float* wq     = (const float*)d_in[7];
    const float* bq     = (const float*)d_in[8];
    const float* wk     = (const float*)d_in[9];
    const float* bk     = (const float*)d_in[10];
    const float* wv     = (const float*)d_in[11];
    const float* bv     = (const float*)d_in[12];
    const float* wskip  = (const float*)d_in[13];
    const float* bskip  = (const float*)d_in[14];
    const float* g_n1   = (const float*)d_in[15];
    const float* be_n1  = (const float*)d_in[16];
    const float* w_m2   = (const float*)d_in[17];
    const float* b_m2   = (const float*)d_in[18];
    const float* g_m2   = (const float*)d_in[19];
    const float* be_m2  = (const float*)d_in[20];
    const float* w_mean = (const float*)d_in[21];
    const float* b_mean = (const float*)d_in[22];
    float* out = (float*)d_out;

    float *h1, *t1, *h2, *s, *agg, *t2, *t3, *h4, *ph;
    __half *h2h, *wqT, *wkT, *wvT, *qh, *kh, *vt, *p;
    cudaGetSymbolAddress((void**)&h1,  g_h1);
    cudaGetSymbolAddress((void**)&t1,  g_t1);
    cudaGetSymbolAddress((void**)&h2,  g_h2);
    cudaGetSymbolAddress((void**)&h2h, g_h2h);
    cudaGetSymbolAddress((void**)&wqT, g_wqT);
    cudaGetSymbolAddress((void**)&wkT, g_wkT);
    cudaGetSymbolAddress((void**)&wvT, g_wvT);
    cudaGetSymbolAddress((void**)&qh,  g_qh);
    cudaGetSymbolAddress((void**)&kh,  g_kh);
    cudaGetSymbolAddress((void**)&vt,  g_vt);
    cudaGetSymbolAddress((void**)&s,   g_s);
    cudaGetSymbolAddress((void**)&p,   g_p);
    cudaGetSymbolAddress((void**)&ph,  g_ph);
    cudaGetSymbolAddress((void**)&agg, g_agg);
    cudaGetSymbolAddress((void**)&t2,  g_t2);
    cudaGetSymbolAddress((void**)&t3,  g_t3);
    cudaGetSymbolAddress((void**)&h4,  g_h4);

    constexpr int SM_SQ = smem_bytes<64, 64, false>();
    cudaFuncSetAttribute(gemm_tc<64, 64, 32, 32, false, 1, true>,
        cudaFuncAttributeMaxDynamicSharedMemorySize, SM_SQ);
    cudaFuncSetAttribute(gemm_tc<64, 64, 32, 32, false, 2, true>,
        cudaFuncAttributeMaxDynamicSharedMemorySize, SM_SQ);
    cudaFuncSetAttribute(gemm_tc<64, 64, 32, 32, false, 0, false>,
        cudaFuncAttributeMaxDynamicSharedMemorySize, SM_SQ);
    cudaFuncSetAttribute(gemm_f16<0>, cudaFuncAttributeMaxDynamicSharedMemorySize, SMEM_F16);
    cudaFuncSetAttribute(gemm_f16<1>, cudaFuncAttributeMaxDynamicSharedMemorySize, SMEM_F16);
    cudaFuncSetAttribute(gemm_f16<2>, cudaFuncAttributeMaxDynamicSharedMemorySize, SMEM_F16);

    const dim3 blk(128);
    const dim3 blk256(256);
    const dim3 gSq(DD_ / 64, NN_ / 64);              // (4, 64)
    const dim3 gOut(OUTD_ / 64, NN_ / 64);           // (2, 64)
    const dim3 gQkv(QKVD_ / 64, NN_ / 128);          // (16, 32)
    const dim3 gScore(NN_ / 64, NN_ / 128, HH_);     // (64, 32, 4)
    const dim3 gPV(DHH_ / 64, NN_ / 128, HH_);       // (4, 32, 4)

    // 0) transpose+convert attention weights to f16 [n][k]
    convT_k<<<QKVD_ * DD_ / 256, blk256>>>(wq, wqT, DD_, QKVD_);
    convT_k<<<QKVD_ * DD_ / 256, blk256>>>(wk, wkT, DD_, QKVD_);
    convT_k<<<QKVD_ * DD_ / 256, blk256>>>(wv, wvT, DD_, QKVD_);

    // 1) h1 = elu(x @ w_in + b_in + x)
    gemm_tc<64, 64, 32, 32, false, 1, true><<<gSq, blk, SM_SQ>>>(x, DD_, 0,
        w_in, DD_, 0, b_in, x, DD_, h1, DD_, 0, DD_, 1.f);

    // 2) t1 = relu(h1 @ w_m1 + b_m1 + h1);  h2 = LN(t1) (f32 + f16)
    gemm_tc<64, 64, 32, 32, false, 2, true><<<gSq, blk, SM_SQ>>>(h1, DD_, 0,
        w_m1, DD_, 0, b_m1, h1, DD_, t1, DD_, 0, DD_, 1.f);
    ln_k<<<NN_, blk256>>>(t1, g_m1, be_m1, h2, h2h);

    // 3) q/k projections (f16 out), v projection (f16 transposed per head)
    gemm_f16<1><<<gQkv, blk, SMEM_F16>>>(h2h, DD_, 0, wqT, DD_, 0,
        bq, qh, QKVD_, 0, DD_, 1.f);
    gemm_f16<1><<<gQkv, blk, SMEM_F16>>>(h2h, DD_, 0, wkT, DD_, 0,
        bk, kh, QKVD_, 0, DD_, 1.f);
    gemm_f16<2><<<gQkv, blk, SMEM_F16>>>(h2h, DD_, 0, wvT, DD_, 0,
        bv, vt, NN_, 0, DD_, 1.f);

    // 4) scores: s[h] = (1/16) * Q_h @ K_h^T   (f32 out)
    gemm_f16<0><<<gScore, blk, SMEM_F16>>>(qh, QKVD_, DHH_, kh, QKVD_, DHH_,
        nullptr, s, NN_, (long)NN_ * NN_, DHH_, 1.f / 16.f);

    // 5) softmax -> f16 probs
    softmax_k<<<HH_ * NN_, blk256>>>(s, p);

    // 6) agg = h2 @ wskip + bskip  (tf32)
    gemm_tc<64, 64, 32, 32, false, 0, false><<<gSq, blk, SM_SQ>>>(h2, DD_, 0,
        wskip, DD_, 0, bskip, nullptr, 0, agg, DD_, 0, DD_, 1.f);

    // 7) per-head PV (alpha=0.25), f32 out into ph[h][n][256]
    gemm_f16<0><<<gPV, blk, SMEM_F16>>>(p, NN_, (long)NN_ * NN_,
        vt, NN_, (long)DHH_ * NN_,
        nullptr, ph, DHH_, (long)NN_ * DHH_, NN_, 0.25f);

    // 8) t2 = LN(agg + sum_h ph)
    ln_agg_k<<<NN_, blk256>>>(agg, ph, g_n1, be_n1, t2);

    // 9) t3 = relu(t2 @ w_m2 + b_m2 + t2);  h4 = LN(t3)
    gemm_tc<64, 64, 32, 32, false, 2, true><<<gSq, blk, SM_SQ>>>(t2, DD_, 0,
        w_m2, DD_, 0, b_m2, t2, DD_, t3, DD_, 0, DD_, 1.f);
    ln_k<<<NN_, blk256>>>(t3, g_m2, be_m2, h4, nullptr);

    // 10) out = h4 @ w_mean + b_mean
    gemm_tc<64, 64, 32, 32, false, 0, false><<<gOut, blk, SM_SQ>>>(h4, DD_, 0,
        w_mean, OUTD_, 0, b_mean, nullptr, 0, out, OUTD_, 0, DD_, 1.f);
}

// round 12
// speedup vs baseline: 1.7200x; 1.4393x over previous
#include <cuda_runtime.h>
#include <cuda_fp16.h>
#include <math.h>
#include <stdint.h>

// Problem dims (fixed)
#define NN_ 4096
#define DD_ 256
#define HH_ 4
#define DHH_ 256
#define QKVD_ 1024
#define OUTD_ 128

// ---------------- scratch (device globals) ------------------------------------
__device__ float g_h1[NN_ * DD_];
__device__ float g_t1[NN_ * DD_];
__device__ float g_h2[NN_ * DD_];
__device__ __align__(16) __half g_h2h[NN_ * DD_];
__device__ __align__(16) __half g_wqT[QKVD_ * DD_];   // [n][k] transposed weights
__device__ __align__(16) __half g_wkT[QKVD_ * DD_];
__device__ __align__(16) __half g_wvT[QKVD_ * DD_];
__device__ __align__(16) __half g_qh[NN_ * QKVD_];    // [n][h*256+d]
__device__ __align__(16) __half g_kh[NN_ * QKVD_];
__device__ __align__(16) __half g_vt[QKVD_ * NN_];    // [h*256+d][m]  (V transposed)
__device__ __align__(16) __half g_p[(size_t)HH_ * NN_ * NN_];  // f16 scores->probs (128 MiB)
__device__ float g_ph[NN_ * QKVD_];                   // per-head PV outputs f32 [h][n][256]
__device__ float g_agg[NN_ * DD_];
__device__ float g_t2[NN_ * DD_];
__device__ float g_t3[NN_ * DD_];
__device__ float g_h4[NN_ * DD_];

__device__ __forceinline__ uint32_t f2tf32(float f) {
    uint32_t u;
    asm("cvt.rna.tf32.f32 %0, %1;" : "=r"(u) : "f"(f));
    return u;
}

__device__ __forceinline__ void mma_tf32(float* d, const uint32_t* a, const uint32_t* b) {
    asm volatile(
        "mma.sync.aligned.m16n8k8.row.col.f32.tf32.tf32.f32 "
        "{%0,%1,%2,%3}, {%4,%5,%6,%7}, {%8,%9}, {%0,%1,%2,%3};\n"
        : "+f"(d[0]), "+f"(d[1]), "+f"(d[2]), "+f"(d[3])
        : "r"(a[0]), "r"(a[1]), "r"(a[2]), "r"(a[3]), "r"(b[0]), "r"(b[1]));
}

__device__ __forceinline__ void mma_f16(float* d, const uint32_t* a, const uint32_t* b) {
    asm volatile(
        "mma.sync.aligned.m16n8k16.row.col.f32.f16.f16.f32 "
        "{%0,%1,%2,%3}, {%4,%5,%6,%7}, {%8,%9}, {%0,%1,%2,%3};\n"
        : "+f"(d[0]), "+f"(d[1]), "+f"(d[2]), "+f"(d[3])
        : "r"(a[0]), "r"(a[1]), "r"(a[2]), "r"(a[3]), "r"(b[0]), "r"(b[1]));
}

__device__ __forceinline__ void cp_async16(void* smem_dst, const void* gmem_src) {
    uint32_t dst = (uint32_t)__cvta_generic_to_shared(smem_dst);
    asm volatile("cp.async.cg.shared.global [%0], [%1], 16;\n"
                 :: "r"(dst), "l"(gmem_src));
}

// ================= FP16 tensor-core GEMM (heavy ops) ===========================
// C = alpha * A @ B^T (+bias), fp32 accumulate.
// A [M][K] f16 row-major; B [N][K] f16 row-major.
// CTA 128x128, 4 warps (2x2), warp tile 64x64 of m16n8k16 atoms, BK=32, 4 stages.
// smem: [rows][16 words], XOR swizzle cw ^= ((r>>1)&3)<<2 -> conflict-free.
// OUTM: 0 = f32 C[m][n]; 1 = f16 C[m][n]+bias; 2 = f16 C[c][m]+bias (transposed);
//       3 = f16 C[m][n] no bias.
template <int OUTM>
__global__ void __launch_bounds__(128, 2) gemm_f16(
    const __half* __restrict__ A, int lda, long sAb,
    const __half* __restrict__ B, int ldb, long sBb,
    const float* __restrict__ bias,
    void* __restrict__ Cv, int ldc, long sCb,
    int K, float alpha)
{
    constexpr int BM = 128, BN = 128, BK = 32, STAGES = 4;
    constexpr int AM = 4, AN = 8;          // warp tile 64x64
    constexpr int AWW = BM * 16;
    constexpr int BWW = BN * 16;

    const int batch = blockIdx.z;
    A += batch * sAb;
    B += batch * sBb;

    extern __shared__ uint32_t smw[];
    uint32_t* Aw = smw;                    // [STAGES][AWW]
    uint32_t* Bw = smw + STAGES * AWW;     // [STAGES][BWW]

    const int t    = threadIdx.x;
    const int warp = t >> 5;
    const int lane = t & 31;
    const int g    = lane >> 2;
    const int tig  = lane & 3;
    const int wm0  = (warp >> 1) * 64;
    const int wn0  = (warp & 1) * 64;
    const int row0 = blockIdx.y * BM;
    const int col0 = blockIdx.x * BN;

    float d[AM][AN][4];
#pragma unroll
    for (int am = 0; am < AM; am++)
#pragma unroll
        for (int an = 0; an < AN; an++)
#pragma unroll
            for (int i = 0; i < 4; i++) d[am][an][i] = 0.f;

    auto issue = [&](int tile, int buf) {
        const int k0 = tile * BK;
        uint32_t* Ad = Aw + buf * AWW;
        uint32_t* Bd = Bw + buf * BWW;
#pragma unroll
        for (int i = 0; i < 4; i++) {          // 512 A chunks (16B)
            int c  = t + i * 128;
            int r  = c >> 2;                   // 0..127
            int wb = (c & 3) * 4;
            cp_async16(Ad + r * 16 + (wb ^ (((r >> 1) & 3) << 2)),
                       A + (long)(row0 + r) * lda + k0 + 2 * wb);
        }
#pragma unroll
        for (int i = 0; i < 4; i++) {          // 512 B chunks
            int c  = t + i * 128;
            int r  = c >> 2;                   // 0..127
            int wb = (c & 3) * 4;
            cp_async16(Bd + r * 16 + (wb ^ (((r >> 1) & 3) << 2)),
                       B + (long)(col0 + r) * ldb + k0 + 2 * wb);
        }
    };

    const int nit = K / BK;

#pragma unroll
    for (int s = 0; s < STAGES - 1; s++) {
        issue(s, s);
        asm volatile("cp.async.commit_group;\n" ::);
    }
    asm volatile("cp.async.wait_group %0;\n" :: "n"(STAGES - 2));
    __syncthreads();

    const int swz = ((g >> 1) & 3) << 2;       // same for rows r and r+8

    for (int it = 0; it < nit; it++) {
        const int buf = it % STAGES;
        const int pf  = it + STAGES - 1;
        if (pf < nit) issue(pf, pf % STAGES);
        asm volatile("cp.async.commit_group;\n" ::);

        const uint32_t* Ab = Aw + buf * AWW;
        const uint32_t* Bb = Bw + buf * BWW;

#pragma unroll
        for (int ks = 0; ks < 2; ks++) {       // two k16 steps per BK=32
            const int kw = ks * 8;
            const int w0 = (kw + tig) ^ swz;
            const int w1 = (kw + tig + 4) ^ swz;
            uint32_t a[AM][4], b[AN][2];
#pragma unroll
            for (int am = 0; am < AM; am++) {
                const int mr = wm0 + am * 16 + g;
                const uint32_t* R0 = Ab + mr * 16;
                const uint32_t* R1 = Ab + (mr + 8) * 16;
                a[am][0] = R0[w0];
                a[am][1] = R1[w0];
                a[am][2] = R0[w1];
                a[am][3] = R1[w1];
            }
#pragma unroll
            for (int an = 0; an < AN; an++) {
                const int nc = wn0 + an * 8 + g;
                b[an][0] = Bb[nc * 16 + w0];
                b[an][1] = Bb[nc * 16 + w1];
            }
#pragma unroll
            for (int am = 0; am < AM; am++)
#pragma unroll
                for (int an = 0; an < AN; an++)
                    mma_f16(d[am][an], a[am], b[an]);
        }

        asm volatile("cp.async.wait_group %0;\n" :: "n"(STAGES - 2));
        __syncthreads();
    }

    // ---- epilogue ----
#pragma unroll
    for (int am = 0; am < AM; am++) {
#pragma unroll
        for (int an = 0; an < AN; an++) {
            const int c0 = col0 + wn0 + an * 8 + tig * 2;
#pragma unroll
            for (int half = 0; half < 2; half++) {
                const int r = row0 + wm0 + am * 16 + g + half * 8;
#pragma unroll
                for (int j = 0; j < 2; j++) {
                    const int c = c0 + j;
                    float v = alpha * d[am][an][half * 2 + j];
                    if (OUTM == 0) {
                        ((float*)Cv)[batch * sCb + (long)r * ldc + c] = v;
                    } else if (OUTM == 1) {
                        v += bias[c];
                        ((__half*)Cv)[batch * sCb + (long)r * ldc + c] = __float2half(v);
                    } else if (OUTM == 2) {
                        v += bias[c];
                        ((__half*)Cv)[batch * sCb + (long)c * ldc + r] = __float2half(v);
                    } else {
                        ((__half*)Cv)[batch * sCb + (long)r * ldc + c] = __float2half(v);
                    }
                }
            }
        }
    }
}
constexpr int SMEM_F16 = 4 * (128 * 16 + 128 * 16) * 4;   // 65536 B

// ================= TF32 GEMM (small square ops), BK=32 =========================
template <int BM, int BN, int WM, int WN, int ACT, bool HAS_RES>
__global__ void __launch_bounds__(128, 3) gemm_tc(
    const float* __restrict__ A, int lda,
    const float* __restrict__ B, int ldb,           // B [K][N] row-major
    const float* __restrict__ bias,
    const float* __restrict__ res, int ldres,
    float* __restrict__ C, int ldc,
    int K, float alpha)
{
    constexpr int BK = 32;
    constexpr int STAGES = 4;
    constexpr int AM = WM / 16;
    constexpr int AN = WN / 8;
    constexpr int PA  = BK + 4;                 // 36
    constexpr int PBN = BN + 8;                 // 72
    constexpr int AW = BM * PA;
    constexpr int BW = BK * PBN;
    constexpr int NCA = BM * BK / (4 * 128);    // 4
    constexpr int NCB = BN * BK / (4 * 128);    // 4
    constexpr int CPA = BK / 4;                 // 8 chunks per A row
    constexpr int CPB = BN / 4;                 // 16 chunks per B row

    extern __shared__ float sm[];
    float* AsB = sm;
    float* BsB = sm + STAGES * AW;

    const int t    = threadIdx.x;
    const int warp = t >> 5;
    const int lane = t & 31;
    const int g    = lane >> 2;
    const int tig  = lane & 3;
    const int wm0  = (warp >> 1) * WM;
    const int wn0  = (warp & 1) * WN;
    const int row0 = blockIdx.y * BM;
    const int col0 = blockIdx.x * BN;

    float d[AM][AN][4];
#pragma unroll
    for (int am = 0; am < AM; am++)
#pragma unroll
        for (int an = 0; an < AN; an++)
#pragma unroll
            for (int i = 0; i < 4; i++) d[am][an][i] = 0.f;

    auto issue_tile = [&](int tile, int buf) {
        const int k0 = tile * BK;
        float* Ad = AsB + buf * AW;
        float* Bd = BsB + buf * BW;
#pragma unroll
        for (int i = 0; i < NCA; i++) {
            int c   = t + i * 128;
            int r   = c / CPA;
            int col = (c % CPA) * 4;
            cp_async16(Ad + r * PA + col, &A[(long)(row0 + r) * lda + k0 + col]);
        }
#pragma unroll
        for (int i = 0; i < NCB; i++) {
            int c   = t + i * 128;
            int r   = c / CPB;
            int col = (c % CPB) * 4;
            cp_async16(Bd + r * PBN + col, &B[(long)(k0 + r) * ldb + col0 + col]);
        }
    };

    const int nit = K / BK;

#pragma unroll
    for (int s = 0; s < STAGES - 1; s++) {
        issue_tile(s, s);
        asm volatile("cp.async.commit_group;\n" ::);
    }
    asm volatile("cp.async.wait_group %0;\n" :: "n"(STAGES - 2));
    __syncthreads();

    for (int it = 0; it < nit; it++) {
        const int buf = it % STAGES;
        const int pf  = it + STAGES - 1;
        if (pf < nit) issue_tile(pf, pf % STAGES);
        asm volatile("cp.async.commit_group;\n" ::);

        const float* Ab = AsB + buf * AW;
        const float* Bb = BsB + buf * BW;

#pragma unroll
        for (int ks = 0; ks < BK / 8; ks++) {
            const int kk = ks * 8;
            uint32_t a[AM][4], b[AN][2];
#pragma unroll
            for (int am = 0; am < AM; am++) {
                const int mr = wm0 + am * 16 + g;
                a[am][0] = f2tf32(Ab[mr * PA + kk + tig]);
                a[am][1] = f2tf32(Ab[(mr + 8) * PA + kk + tig]);
                a[am][2] = f2tf32(Ab[mr * PA + kk + tig + 4]);
                a[am][3] = f2tf32(Ab[(mr + 8) * PA + kk + tig + 4]);
            }
#pragma unroll
            for (int an = 0; an < AN; an++) {
                const int nc = wn0 + an * 8 + g;
                b[an][0] = f2tf32(Bb[(kk + tig) * PBN + nc]);
                b[an][1] = f2tf32(Bb[(kk + tig + 4) * PBN + nc]);
            }
#pragma unroll
            for (int am = 0; am < AM; am++)
#pragma unroll
                for (int an = 0; an < AN; an++)
                    mma_tf32(d[am][an], a[am], b[an]);
        }

        asm volatile("cp.async.wait_group %0;\n" :: "n"(STAGES - 2));
        __syncthreads();
    }

#pragma unroll
    for (int am = 0; am < AM; am++) {
#pragma unroll
        for (int an = 0; an < AN; an++) {
            const int c0 = col0 + wn0 + an * 8 + tig * 2;
#pragma unroll
            for (int half = 0; half < 2; half++) {
                const int r = row0 + wm0 + am * 16 + g + half * 8;
#pragma unroll
                for (int j = 0; j < 2; j++) {
                    const int c = c0 + j;
                    float v = alpha * d[am][an][half * 2 + j];
                    if (bias) v += bias[c];
                    if (HAS_RES) v += res[(long)r * ldres + c];
                    if (ACT == 1) v = (v > 0.f) ? v : expm1f(v);
                    if (ACT == 2) v = fmaxf(v, 0.f);
                    C[(long)r * ldc + c] = v;
                }
            }
        }
    }
}

template <int BM, int BN>
constexpr int smem_bytes() {
    constexpr int BK = 32, STAGES = 4;
    return STAGES * (BM * (BK + 4) + BK * (BN + 8)) * 4;
}

// ---------------- weight transpose+convert: wT[n][k] = f16(w[k][n]) ------------
__global__ void convT_k(const float* __restrict__ w, __half* __restrict__ wt, int Kin, int Nout)
{
    int i = blockIdx.x * 256 + threadIdx.x;
    int n = i / Kin, k = i - n * Kin;
    wt[i] = __float2half(w[(long)k * Nout + n]);
}

// ---------------- block reduce (256 threads) -----------------------------------
__device__ __forceinline__ float block_reduce_256(float v, bool do_max)
{
    __shared__ float sm[8];
#pragma unroll
    for (int o = 16; o > 0; o >>= 1) {
        float u = __shfl_xor_sync(0xffffffffu, v, o);
        v = do_max ? fmaxf(v, u) : (v + u);
    }
    const int warp = threadIdx.x >> 5;
    if ((threadIdx.x & 31) == 0) sm[warp] = v;
    __syncthreads();
    float r = sm[0];
#pragma unroll
    for (int i = 1; i < 8; i++) r = do_max ? fmaxf(r, sm[i]) : (r + sm[i]);
    __syncthreads();
    return r;
}

// ---------------- softmax over rows of 4096: f16 in -> f16 out (in place) ------
__global__ void __launch_bounds__(256) softmax_h(__half* __restrict__ P)
{
    const long row = blockIdx.x;
    __half2* p = reinterpret_cast<__half2*>(P + row * (long)NN_);
    const int t = threadIdx.x;

    float2 v[8];
    float m = -1e30f;
#pragma unroll
    for (int i = 0; i < 8; i++) {
        v[i] = __half22float2(p[i * 256 + t]);
        m = fmaxf(m, fmaxf(v[i].x, v[i].y));
    }
    m = block_reduce_256(m, true);

    float s = 0.f;
#pragma unroll
    for (int i = 0; i < 8; i++) {
        v[i].x = __expf(v[i].x - m);
        v[i].y = __expf(v[i].y - m);
        s += v[i].x + v[i].y;
    }
    s = block_reduce_256(s, false);

    const float inv = 1.f / s;
#pragma unroll
    for (int i = 0; i < 8; i++)
        p[i * 256 + t] = __floats2half2_rn(v[i].x * inv, v[i].y * inv);
}

// ---------------- LayerNorm over rows of 256 (optional f16 secondary out) ------
__global__ void __launch_bounds__(256) ln_k(
    const float* __restrict__ X, const float* __restrict__ g,
    const float* __restrict__ b, float* __restrict__ Y, __half* __restrict__ Y16)
{
    const int row = blockIdx.x;
    const int t = threadIdx.x;
    const float x = X[row * DD_ + t];
    const float mean = block_reduce_256(x, false) * (1.f / 256.f);
    const float d = x - mean;
    const float var = block_reduce_256(d * d, false) * (1.f / 256.f);
    const float y = d * rsqrtf(var + 1e-5f) * g[t] + b[t];
    Y[row * DD_ + t] = y;
    if (Y16) Y16[row * DD_ + t] = __float2half(y);
}

// ---- LN of (skip + sum of 4 per-head PV outputs), heads pre-scaled by 0.25 ----
__global__ void __launch_bounds__(256) ln_agg_k(
    const float* __restrict__ skip, const float* __restrict__ ph,
    const float* __restrict__ g, const float* __restrict__ b,
    float* __restrict__ Y)
{
    const int row = blockIdx.x;
    const int t = threadIdx.x;
    const long i = (long)row * DD_ + t;
    const long S = (long)NN_ * DD_;
    const float x = skip[i] + ph[i] + ph[i + S] + ph[i + 2 * S] + ph[i + 3 * S];
    const float mean = block_reduce_256(x, false) * (1.f / 256.f);
    const float d = x - mean;
    const float var = block_reduce_256(d * d, false) * (1.f / 256.f);
    Y[row * DD_ + t] = d * rsqrtf(var + 1e-5f) * g[t] + b[t];
}

// ---------------- launch --------------------------------------------------------
extern "C" void kernel_launch(void* const* d_in, const int* in_sizes, int n_in,
                              void* d_out, int out_size)
{
    const float* x      = (const float*)d_in[0];
    const float* w_in   = (const float*)d_in[1];
    const float* b_in   = (const float*)d_in[2];
    const float* w_m1   = (const float*)d_in[3];
    const float* b_m1   = (const float*)d_in[4];
    const float* g_m1   = (const float*)d_in[5];
    const float* be_m1  = (const float*)d_in[6];
    const float* wq     = (const float*)d_in[7];
    const float* bq     = (const float*)d_in[8];
    const float* wk     = (const float*)d_in[9];
    const float* bk     = (const float*)d_in[10];
    const float* wv     = (const float*)d_in[11];
    const float* bv     = (const float*)d_in[12];
    const float* wskip  = (const float*)d_in[13];
    const float* bskip  = (const float*)d_in[14];
    const float* g_n1   = (const float*)d_in[15];
    const float* be_n1  = (const float*)d_in[16];
    const float* w_m2   = (const float*)d_in[17];
    const float* b_m2   = (const float*)d_in[18];
    const float* g_m2   = (const float*)d_in[19];
    const float* be_m2  = (const float*)d_in[20];
    const float* w_mean = (const float*)d_in[21];
    const float* b_mean = (const float*)d_in[22];
    float* out = (float*)d_out;

    float *h1, *t1, *h2, *agg, *t2, *t3, *h4, *ph;
    __half *h2h, *wqT, *wkT, *wvT, *qh, *kh, *vt, *p;
    cudaGetSymbolAddress((void**)&h1,  g_h1);
    cudaGetSymbolAddress((void**)&t1,  g_t1);
    cudaGetSymbolAddress((void**)&h2,  g_h2);
    cudaGetSymbolAddress((void**)&h2h, g_h2h);
    cudaGetSymbolAddress((void**)&wqT, g_wqT);
    cudaGetSymbolAddress((void**)&wkT, g_wkT);
    cudaGetSymbolAddress((void**)&wvT, g_wvT);
    cudaGetSymbolAddress((void**)&qh,  g_qh);
    cudaGetSymbolAddress((void**)&kh,  g_kh);
    cudaGetSymbolAddress((void**)&vt,  g_vt);
    cudaGetSymbolAddress((void**)&p,   g_p);
    cudaGetSymbolAddress((void**)&ph,  g_ph);
    cudaGetSymbolAddress((void**)&agg, g_agg);
    cudaGetSymbolAddress((void**)&t2,  g_t2);
    cudaGetSymbolAddress((void**)&t3,  g_t3);
    cudaGetSymbolAddress((void**)&h4,  g_h4);

    constexpr int SM_SQ = smem_bytes<64, 64>();
    cudaFuncSetAttribute(gemm_tc<64, 64, 32, 32, 1, true>,
        cudaFuncAttributeMaxDynamicSharedMemorySize, SM_SQ);
    cudaFuncSetAttribute(gemm_tc<64, 64, 32, 32, 2, true>,
        cudaFuncAttributeMaxDynamicSharedMemorySize, SM_SQ);
    cudaFuncSetAttribute(gemm_tc<64, 64, 32, 32, 0, false>,
        cudaFuncAttributeMaxDynamicSharedMemorySize, SM_SQ);
    cudaFuncSetAttribute(gemm_f16<0>, cudaFuncAttributeMaxDynamicSharedMemorySize, SMEM_F16);
    cudaFuncSetAttribute(gemm_f16<1>, cudaFuncAttributeMaxDynamicSharedMemorySize, SMEM_F16);
    cudaFuncSetAttribute(gemm_f16<2>, cudaFuncAttributeMaxDynamicSharedMemorySize, SMEM_F16);
    cudaFuncSetAttribute(gemm_f16<3>, cudaFuncAttributeMaxDynamicSharedMemorySize, SMEM_F16);

    const dim3 blk(128);
    const dim3 blk256(256);
    const dim3 gSq(DD_ / 64, NN_ / 64);              // (4, 64)
    const dim3 gOut(OUTD_ / 64, NN_ / 64);           // (2, 64)
    const dim3 gQkv(QKVD_ / 128, NN_ / 128);         // (8, 32)
    const dim3 gScore(NN_ / 128, NN_ / 128, HH_);    // (32, 32, 4)
    const dim3 gPV(DHH_ / 128, NN_ / 128, HH_);      // (2, 32, 4)

    // 0) transpose+convert attention weights to f16 [n][k]
    convT_k<<<QKVD_ * DD_ / 256, blk256>>>(wq, wqT, DD_, QKVD_);
    convT_k<<<QKVD_ * DD_ / 256, blk256>>>(wk, wkT, DD_, QKVD_);
    convT_k<<<QKVD_ * DD_ / 256, blk256>>>(wv, wvT, DD_, QKVD_);

    // 1) h1 = elu(x @ w_in + b_in + x)
    gemm_tc<64, 64, 32, 32, 1, true><<<gSq, blk, SM_SQ>>>(x, DD_,
        w_in, DD_, b_in, x, DD_, h1, DD_, DD_, 1.f);

    // 2) t1 = relu(h1 @ w_m1 + b_m1 + h1);  h2 = LN(t1) (f32 + f16)
    gemm_tc<64, 64, 32, 32, 2, true><<<gSq, blk, SM_SQ>>>(h1, DD_,
        w_m1, DD_, b_m1, h1, DD_, t1, DD_, DD_, 1.f);
    ln_k<<<NN_, blk256>>>(t1, g_m1, be_m1, h2, h2h);

    // 3) q/k projections (f16 out), v projection (f16 transposed per head)
    gemm_f16<1><<<gQkv, blk, SMEM_F16>>>(h2h, DD_, 0, wqT, DD_, 0,
        bq, qh, QKVD_, 0, DD_, 1.f);
    gemm_f16<1><<<gQkv, blk, SMEM_F16>>>(h2h, DD_, 0, wkT, DD_, 0,
        bk, kh, QKVD_, 0, DD_, 1.f);
    gemm_f16<2><<<gQkv, blk, SMEM_F16>>>(h2h, DD_, 0, wvT, DD_, 0,
        bv, vt, NN_, 0, DD_, 1.f);

    // 4) scores: p[h] = f16((1/16) * Q_h @ K_h^T)
    gemm_f16<3><<<gScore, blk, SMEM_F16>>>(qh, QKVD_, DHH_, kh, QKVD_, DHH_,
        nullptr, p, NN_, (long)NN_ * NN_, DHH_, 1.f / 16.f);

    // 5) softmax in place on f16
    softmax_h<<<HH_ * NN_, blk256>>>(p);

    // 6) agg = h2 @ wskip + bskip  (tf32)
    gemm_tc<64, 64, 32, 32, 0, false><<<gSq, blk, SM_SQ>>>(h2, DD_,
        wskip, DD_, bskip, nullptr, 0, agg, DD_, DD_, 1.f);

    // 7) per-head PV (alpha=0.25), f32 out into ph[h][n][256]
    gemm_f16<0><<<gPV, blk, SMEM_F16>>>(p, NN_, (long)NN_ * NN_,
        vt, NN_, (long)DHH_ * NN_,
        nullptr, ph, DHH_, (long)NN_ * DHH_, NN_, 0.25f);

    // 8) t2 = LN(agg + sum_h ph)
    ln_agg_k<<<NN_, blk256>>>(agg, ph, g_n1, be_n1, t2);

    // 9) t3 = relu(t2 @ w_m2 + b_m2 + t2);  h4 = LN(t3)
    gemm_tc<64, 64, 32, 32, 2, true><<<gSq, blk, SM_SQ>>>(t2, DD_,
        w_m2, DD_, b_m2, t2, DD_, t3, DD_, DD_, 1.f);
    ln_k<<<NN_, blk256>>>(t3, g_m2, be_m2, h4, nullptr);

    // 10) out = h4 @ w_mean + b_mean
    gemm_tc<64, 64, 32, 32, 0, false><<<gOut, blk, SM_SQ>>>(h4, DD_,
        w_mean, OUTD_, b_mean, nullptr, 0, out, OUTD_, DD_, 1.f);
}

// round 14
// speedup vs baseline: 1.8691x; 1.0867x over previous
#include <cuda_runtime.h>
#include <cuda_fp16.h>
#include <math.h>
#include <stdint.h>

// Problem dims (fixed)
#define NN_ 4096
#define DD_ 256
#define HH_ 4
#define DHH_ 256
#define QKVD_ 1024
#define OUTD_ 128

// ---------------- scratch (device globals) ------------------------------------
__device__ float g_h1[NN_ * DD_];
__device__ float g_t1[NN_ * DD_];
__device__ float g_h2[NN_ * DD_];
__device__ __align__(16) __half g_h2h[NN_ * DD_];
__device__ __align__(16) __half g_wqT[QKVD_ * DD_];   // [n][k] transposed weights
__device__ __align__(16) __half g_wkT[QKVD_ * DD_];
__device__ __align__(16) __half g_wvT[QKVD_ * DD_];
__device__ __align__(16) __half g_qh[NN_ * QKVD_];    // [n][h*256+d]
__device__ __align__(16) __half g_kh[NN_ * QKVD_];
__device__ __align__(16) __half g_vt[QKVD_ * NN_];    // [h*256+d][m]  (V transposed)
__device__ __align__(16) __half g_p[(size_t)HH_ * NN_ * NN_];  // f16 scores->probs (128 MiB)
__device__ float g_ph[NN_ * QKVD_];                   // per-head PV outputs f32 [h][n][256]
__device__ float g_agg[NN_ * DD_];
__device__ float g_t2[NN_ * DD_];
__device__ float g_t3[NN_ * DD_];
__device__ float g_h4[NN_ * DD_];

__device__ __forceinline__ uint32_t f2tf32(float f) {
    uint32_t u;
    asm("cvt.rna.tf32.f32 %0, %1;" : "=r"(u) : "f"(f));
    return u;
}

__device__ __forceinline__ void mma_tf32(float* d, const uint32_t* a, const uint32_t* b) {
    asm volatile(
        "mma.sync.aligned.m16n8k8.row.col.f32.tf32.tf32.f32 "
        "{%0,%1,%2,%3}, {%4,%5,%6,%7}, {%8,%9}, {%0,%1,%2,%3};\n"
        : "+f"(d[0]), "+f"(d[1]), "+f"(d[2]), "+f"(d[3])
        : "r"(a[0]), "r"(a[1]), "r"(a[2]), "r"(a[3]), "r"(b[0]), "r"(b[1]));
}

__device__ __forceinline__ void mma_f16(float* d, const uint32_t* a, const uint32_t* b) {
    asm volatile(
        "mma.sync.aligned.m16n8k16.row.col.f32.f16.f16.f32 "
        "{%0,%1,%2,%3}, {%4,%5,%6,%7}, {%8,%9}, {%0,%1,%2,%3};\n"
        : "+f"(d[0]), "+f"(d[1]), "+f"(d[2]), "+f"(d[3])
        : "r"(a[0]), "r"(a[1]), "r"(a[2]), "r"(a[3]), "r"(b[0]), "r"(b[1]));
}

__device__ __forceinline__ void ldsm_x4(uint32_t* r, uint32_t addr) {
    asm volatile(
        "ldmatrix.sync.aligned.m8n8.x4.shared.b16 {%0,%1,%2,%3}, [%4];\n"
        : "=r"(r[0]), "=r"(r[1]), "=r"(r[2]), "=r"(r[3]) : "r"(addr));
}

__device__ __forceinline__ void cp_async16(void* smem_dst, const void* gmem_src) {
    uint32_t dst = (uint32_t)__cvta_generic_to_shared(smem_dst);
    asm volatile("cp.async.cg.shared.global [%0], [%1], 16;\n"
                 :: "r"(dst), "l"(gmem_src));
}

// ================= FP16 tensor-core GEMM (heavy ops) ===========================
// C = alpha * A @ B^T (+bias), fp32 accumulate.
// A [M][K] f16 row-major; B [N][K] f16 row-major.
// CTA 128x128, 4 warps (2x2), warp tile 64x64 of m16n8k16 atoms, BK=32, 4 stages.
// smem: [rows][16 words], XOR swizzle word-bits[2:3] ^= (r>>1)&3 -> 16B chunks
// stay contiguous; fragment loads via ldmatrix.x4 (4 regs/instr), conflict-free.
// OUTM: 0 = f32 C[m][n]; 1 = f16 C[m][n]+bias; 2 = f16 C[c][m]+bias (transposed);
//       3 = f16 C[m][n] no bias.
template <int OUTM>
__global__ void __launch_bounds__(128, 2) gemm_f16(
    const __half* __restrict__ A, int lda, long sAb,
    const __half* __restrict__ B, int ldb, long sBb,
    const float* __restrict__ bias,
    void* __restrict__ Cv, int ldc, long sCb,
    int K, float alpha)
{
    constexpr int BM = 128, BN = 128, BK = 32, STAGES = 4;
    constexpr int AM = 4, AN = 8;          // warp tile 64x64
    constexpr int AWW = BM * 16;
    constexpr int BWW = BN * 16;

    const int batch = blockIdx.z;
    A += batch * sAb;
    B += batch * sBb;

    extern __shared__ uint32_t smw[];
    uint32_t* Aw = smw;                    // [STAGES][AWW]
    uint32_t* Bw = smw + STAGES * AWW;     // [STAGES][BWW]

    const int t    = threadIdx.x;
    const int warp = t >> 5;
    const int lane = t & 31;
    const int g    = lane >> 2;
    const int tig  = lane & 3;
    const int wm0  = (warp >> 1) * 64;
    const int wn0  = (warp & 1) * 64;
    const int row0 = blockIdx.y * BM;
    const int col0 = blockIdx.x * BN;

    float d[AM][AN][4];
#pragma unroll
    for (int am = 0; am < AM; am++)
#pragma unroll
        for (int an = 0; an < AN; an++)
#pragma unroll
            for (int i = 0; i < 4; i++) d[am][an][i] = 0.f;

    auto issue = [&](int tile, int buf) {
        const int k0 = tile * BK;
        uint32_t* Ad = Aw + buf * AWW;
        uint32_t* Bd = Bw + buf * BWW;
#pragma unroll
        for (int i = 0; i < 4; i++) {          // 512 A chunks (16B)
            int c  = t + i * 128;
            int r  = c >> 2;                   // 0..127
            int wb = (c & 3) * 4;
            cp_async16(Ad + r * 16 + (wb ^ (((r >> 1) & 3) << 2)),
                       A + (long)(row0 + r) * lda + k0 + 2 * wb);
        }
#pragma unroll
        for (int i = 0; i < 4; i++) {          // 512 B chunks
            int c  = t + i * 128;
            int r  = c >> 2;                   // 0..127
            int wb = (c & 3) * 4;
            cp_async16(Bd + r * 16 + (wb ^ (((r >> 1) & 3) << 2)),
                       B + (long)(col0 + r) * ldb + k0 + 2 * wb);
        }
    };

    const int nit = K / BK;

#pragma unroll
    for (int s = 0; s < STAGES - 1; s++) {
        issue(s, s);
        asm volatile("cp.async.commit_group;\n" ::);
    }
    asm volatile("cp.async.wait_group %0;\n" :: "n"(STAGES - 2));
    __syncthreads();

    // ---- per-thread ldmatrix address bases (byte units) ----
    const uint32_t smem_u = (uint32_t)__cvta_generic_to_shared(smw);
    // A: lanes 0-7 mat0 (rows+0..7, kw), 8-15 mat1 (rows+8..15, kw),
    //    16-23 mat2 (rows+0..7, kw+4), 24-31 mat3 (rows+8..15, kw+4)
    const int laneAr = lane & 15;               // row within m16 atom
    const uint32_t laneAk = (uint32_t)((lane >> 4) << 2);   // +4 words for k-half
    const uint32_t sAx = (uint32_t)(((laneAr >> 1) & 3) << 2);
    const uint32_t kwA0 = ((0u + laneAk) ^ sAx) * 4u;
    const uint32_t kwA8 = ((8u + laneAk) ^ sAx) * 4u;
    const uint32_t baseA = smem_u + (uint32_t)(wm0 + laneAr) * 64u;
    // B: mats = (atom an: rows na..na+7 / na+8..15) x (kw / kw+4):
    //    reg order r0=b[an][0], r1=b[an][1], r2=b[an+1][0], r3=b[an+1][1]
    const int laneBr = ((lane >> 4) << 3) + (lane & 7);     // row within n16 pair
    const uint32_t laneBk = (uint32_t)(((lane >> 3) & 1) << 2);
    const uint32_t sBx = (uint32_t)(((laneBr >> 1) & 3) << 2);
    const uint32_t kwB0 = ((0u + laneBk) ^ sBx) * 4u;
    const uint32_t kwB8 = ((8u + laneBk) ^ sBx) * 4u;
    const uint32_t baseB = smem_u + (uint32_t)(STAGES * AWW) * 4u
                         + (uint32_t)(wn0 + laneBr) * 64u;

    for (int it = 0; it < nit; it++) {
        const int buf = it % STAGES;
        const int pf  = it + STAGES - 1;
        if (pf < nit) issue(pf, pf % STAGES);
        asm volatile("cp.async.commit_group;\n" ::);

        const uint32_t Abuf = baseA + (uint32_t)(buf * AWW) * 4u;
        const uint32_t Bbuf = baseB + (uint32_t)(buf * BWW) * 4u;

#pragma unroll
        for (int ks = 0; ks < 2; ks++) {       // two k16 steps per BK=32
            const uint32_t ka = ks ? kwA8 : kwA0;
            const uint32_t kb = ks ? kwB8 : kwB0;
            uint32_t a[AM][4], b[AN][2];
#pragma unroll
            for (int am = 0; am < AM; am++)
                ldsm_x4(a[am], Abuf + (uint32_t)(am * 1024) + ka);
#pragma unroll
            for (int anp = 0; anp < AN / 2; anp++) {
                uint32_t b4[4];
                ldsm_x4(b4, Bbuf + (uint32_t)(anp * 1024) + kb);
                b[2 * anp][0]     = b4[0];
                b[2 * anp][1]     = b4[1];
                b[2 * anp + 1][0] = b4[2];
                b[2 * anp + 1][1] = b4[3];
            }
#pragma unroll
            for (int am = 0; am < AM; am++)
#pragma unroll
                for (int an = 0; an < AN; an++)
                    mma_f16(d[am][an], a[am], b[an]);
        }

        asm volatile("cp.async.wait_group %0;\n" :: "n"(STAGES - 2));
        __syncthreads();
    }

    // ---- epilogue ----
#pragma unroll
    for (int am = 0; am < AM; am++) {
#pragma unroll
        for (int an = 0; an < AN; an++) {
            const int c0 = col0 + wn0 + an * 8 + tig * 2;
#pragma unroll
            for (int half = 0; half < 2; half++) {
                const int r = row0 + wm0 + am * 16 + g + half * 8;
#pragma unroll
                for (int j = 0; j < 2; j++) {
                    const int c = c0 + j;
                    float v = alpha * d[am][an][half * 2 + j];
                    if (OUTM == 0) {
                        ((float*)Cv)[batch * sCb + (long)r * ldc + c] = v;
                    } else if (OUTM == 1) {
                        v += bias[c];
                        ((__half*)Cv)[batch * sCb + (long)r * ldc + c] = __float2half(v);
                    } else if (OUTM == 2) {
                        v += bias[c];
                        ((__half*)Cv)[batch * sCb + (long)c * ldc + r] = __float2half(v);
                    } else {
                        ((__half*)Cv)[batch * sCb + (long)r * ldc + c] = __float2half(v);
                    }
                }
            }
        }
    }
}
constexpr int SMEM_F16 = 4 * (128 * 16 + 128 * 16) * 4;   // 65536 B

// ================= TF32 GEMM (small square ops), BK=32 =========================
template <int BM, int BN, int WM, int WN, int ACT, bool HAS_RES>
__global__ void __launch_bounds__(128, 3) gemm_tc(
    const float* __restrict__ A, int lda,
    const float* __restrict__ B, int ldb,           // B [K][N] row-major
    const float* __restrict__ bias,
    const float* __restrict__ res, int ldres,
    float* __restrict__ C, int ldc,
    int K, float alpha)
{
    constexpr int BK = 32;
    constexpr int STAGES = 4;
    constexpr int AM = WM / 16;
    constexpr int AN = WN / 8;
    constexpr int PA  = BK + 4;                 // 36
    constexpr int PBN = BN + 8;                 // 72
    constexpr int AW = BM * PA;
    constexpr int BW = BK * PBN;
    constexpr int NCA = BM * BK / (4 * 128);    // 4
    constexpr int NCB = BN * BK / (4 * 128);    // 4
    constexpr int CPA = BK / 4;                 // 8 chunks per A row
    constexpr int CPB = BN / 4;                 // 16 chunks per B row

    extern __shared__ float sm[];
    float* AsB = sm;
    float* BsB = sm + STAGES * AW;

    const int t    = threadIdx.x;
    const int warp = t >> 5;
    const int lane = t & 31;
    const int g    = lane >> 2;
    const int tig  = lane & 3;
    const int wm0  = (warp >> 1) * WM;
    const int wn0  = (warp & 1) * WN;
    const int row0 = blockIdx.y * BM;
    const int col0 = blockIdx.x * BN;

    float d[AM][AN][4];
#pragma unroll
    for (int am = 0; am < AM; am++)
#pragma unroll
        for (int an = 0; an < AN; an++)
#pragma unroll
            for (int i = 0; i < 4; i++) d[am][an][i] = 0.f;

    auto issue_tile = [&](int tile, int buf) {
        const int k0 = tile * BK;
        float* Ad = AsB + buf * AW;
        float* Bd = BsB + buf * BW;
#pragma unroll
        for (int i = 0; i < NCA; i++) {
            int c   = t + i * 128;
            int r   = c / CPA;
            int col = (c % CPA) * 4;
            cp_async16(Ad + r * PA + col, &A[(long)(row0 + r) * lda + k0 + col]);
        }
#pragma unroll
        for (int i = 0; i < NCB; i++) {
            int c   = t + i * 128;
            int r   = c / CPB;
            int col = (c % CPB) * 4;
            cp_async16(Bd + r * PBN + col, &B[(long)(k0 + r) * ldb + col0 + col]);
        }
    };

    const int nit = K / BK;

#pragma unroll
    for (int s = 0; s < STAGES - 1; s++) {
        issue_tile(s, s);
        asm volatile("cp.async.commit_group;\n" ::);
    }
    asm volatile("cp.async.wait_group %0;\n" :: "n"(STAGES - 2));
    __syncthreads();

    for (int it = 0; it < nit; it++) {
        const int buf = it % STAGES;
        const int pf  = it + STAGES - 1;
        if (pf < nit) issue_tile(pf, pf % STAGES);
        asm volatile("cp.async.commit_group;\n" ::);

        const float* Ab = AsB + buf * AW;
        const float* Bb = BsB + buf * BW;

#pragma unroll
        for (int ks = 0; ks < BK / 8; ks++) {
            const int kk = ks * 8;
            uint32_t a[AM][4], b[AN][2];
#pragma unroll
            for (int am = 0; am < AM; am++) {
                const int mr = wm0 + am * 16 + g;
                a[am][0] = f2tf32(Ab[mr * PA + kk + tig]);
                a[am][1] = f2tf32(Ab[(mr + 8) * PA + kk + tig]);
                a[am][2] = f2tf32(Ab[mr * PA + kk + tig + 4]);
                a[am][3] = f2tf32(Ab[(mr + 8) * PA + kk + tig + 4]);
            }
#pragma unroll
            for (int an = 0; an < AN; an++) {
                const int nc = wn0 + an * 8 + g;
                b[an][0] = f2tf32(Bb[(kk + tig) * PBN + nc]);
                b[an][1] = f2tf32(Bb[(kk + tig + 4) * PBN + nc]);
            }
#pragma unroll
            for (int am = 0; am < AM; am++)
#pragma unroll
                for (int an = 0; an < AN; an++)
                    mma_tf32(d[am][an], a[am], b[an]);
        }

        asm volatile("cp.async.wait_group %0;\n" :: "n"(STAGES - 2));
        __syncthreads();
    }

#pragma unroll
    for (int am = 0; am < AM; am++) {
#pragma unroll
        for (int an = 0; an < AN; an++) {
            const int c0 = col0 + wn0 + an * 8 + tig * 2;
#pragma unroll
            for (int half = 0; half < 2; half++) {
                const int r = row0 + wm0 + am * 16 + g + half * 8;
#pragma unroll
                for (int j = 0; j < 2; j++) {
                    const int c = c0 + j;
                    float v = alpha * d[am][an][half * 2 + j];
                    if (bias) v += bias[c];
                    if (HAS_RES) v += res[(long)r * ldres + c];
                    if (ACT == 1) v = (v > 0.f) ? v : expm1f(v);
                    if (ACT == 2) v = fmaxf(v, 0.f);
                    C[(long)r * ldc + c] = v;
                }
            }
        }
    }
}

template <int BM, int BN>
constexpr int smem_bytes() {
    constexpr int BK = 32, STAGES = 4;
    return STAGES * (BM * (BK + 4) + BK * (BN + 8)) * 4;
}

// ---------------- weight transpose+convert: wT[n][k] = f16(w[k][n]) ------------
__global__ void convT_k(const float* __restrict__ w, __half* __restrict__ wt, int Kin, int Nout)
{
    int i = blockIdx.x * 256 + threadIdx.x;
    int n = i / Kin, k = i - n * Kin;
    wt[i] = __float2half(w[(long)k * Nout + n]);
}

// ---------------- block reduce (256 threads) -----------------------------------
__device__ __forceinline__ float block_reduce_256(float v, bool do_max)
{
    __shared__ float sm[8];
#pragma unroll
    for (int o = 16; o > 0; o >>= 1) {
        float u = __shfl_xor_sync(0xffffffffu, v, o);
        v = do_max ? fmaxf(v, u) : (v + u);
    }
    const int warp = threadIdx.x >> 5;
    if ((threadIdx.x & 31) == 0) sm[warp] = v;
    __syncthreads();
    float r = sm[0];
#pragma unroll
    for (int i = 1; i < 8; i++) r = do_max ? fmaxf(r, sm[i]) : (r + sm[i]);
    __syncthreads();
    return r;
}

// ---------------- softmax over rows of 4096: f16 in -> f16 out (in place) ------
__global__ void __launch_bounds__(256) softmax_h(__half* __restrict__ P)
{
    const long row = blockIdx.x;
    __half2* p = reinterpret_cast<__half2*>(P + row * (long)NN_);
    const int t = threadIdx.x;

    float2 v[8];
    float m = -1e30f;
#pragma unroll
    for (int i = 0; i < 8; i++) {
        v[i] = __half22float2(p[i * 256 + t]);
        m = fmaxf(m, fmaxf(v[i].x, v[i].y));
    }
    m = block_reduce_256(m, true);

    float s = 0.f;
#pragma unroll
    for (int i = 0; i < 8; i++) {
        v[i].x = __expf(v[i].x - m);
        v[i].y = __expf(v[i].y - m);
        s += v[i].x + v[i].y;
    }
    s = block_reduce_256(s, false);

    const float inv = 1.f / s;
#pragma unroll
    for (int i = 0; i < 8; i++)
        p[i * 256 + t] = __floats2half2_rn(v[i].x * inv, v[i].y * inv);
}

// ---------------- LayerNorm over rows of 256 (optional f16 secondary out) ------
__global__ void __launch_bounds__(256) ln_k(
    const float* __restrict__ X, const float* __restrict__ g,
    const float* __restrict__ b, float* __restrict__ Y, __half* __restrict__ Y16)
{
    const int row = blockIdx.x;
    const int t = threadIdx.x;
    const float x = X[row * DD_ + t];
    const float mean = block_reduce_256(x, false) * (1.f / 256.f);
    const float d = x - mean;
    const float var = block_reduce_256(d * d, false) * (1.f / 256.f);
    const float y = d * rsqrtf(var + 1e-5f) * g[t] + b[t];
    Y[row * DD_ + t] = y;
    if (Y16) Y16[row * DD_ + t] = __float2half(y);
}

// ---- LN of (skip + sum of 4 per-head PV outputs), heads pre-scaled by 0.25 ----
__global__ void __launch_bounds__(256) ln_agg_k(
    const float* __restrict__ skip, const float* __restrict__ ph,
    const float* __restrict__ g, const float* __restrict__ b,
    float* __restrict__ Y)
{
    const int row = blockIdx.x;
    const int t = threadIdx.x;
    const long i = (long)row * DD_ + t;
    const long S = (long)NN_ * DD_;
    const float x = skip[i] + ph[i] + ph[i + S] + ph[i + 2 * S] + ph[i + 3 * S];
    const float mean = block_reduce_256(x, false) * (1.f / 256.f);
    const float d = x - mean;
    const float var = block_reduce_256(d * d, false) * (1.f / 256.f);
    Y[row * DD_ + t] = d * rsqrtf(var + 1e-5f) * g[t] + b[t];
}

// ---------------- launch --------------------------------------------------------
extern "C" void kernel_launch(void* const* d_in, const int* in_sizes, int n_in,
                              void* d_out, int out_size)
{
    const float* x      = (const float*)d_in[0];
    const float* w_in   = (const float*)d_in[1];
    const float* b_in   = (const float*)d_in[2];
    const float* w_m1   = (const float*)d_in[3];
    const float* b_m1   = (const float*)d_in[4];
    const float* g_m1   = (const float*)d_in[5];
    const float* be_m1  = (const float*)d_in[6];
    const float* wq     = (const float*)d_in[7];
    const float* bq     = (const float*)d_in[8];
    const float* wk     = (const float*)d_in[9];
    const float* bk     = (const float*)d_in[10];
    const float* wv     = (const float*)d_in[11];
    const float* bv     = (const float*)d_in[12];
    const float* wskip  = (const float*)d_in[13];
    const float* bskip  = (const float*)d_in[14];
    const float* g_n1   = (const float*)d_in[15];
    const float* be_n1  = (const float*)d_in[16];
    const float* w_m2   = (const float*)d_in[17];
    const float* b_m2   = (const float*)d_in[18];
    const float* g_m2   = (const float*)d_in[19];
    const float* be_m2  = (const float*)d_in[20];
    const float* w_mean = (const float*)d_in[21];
    const float* b_mean = (const float*)d_in[22];
    float* out = (float*)d_out;

    float *h1, *t1, *h2, *agg, *t2, *t3, *h4, *ph;
    __half *h2h, *wqT, *wkT, *wvT, *qh, *kh, *vt, *p;
    cudaGetSymbolAddress((void**)&h1,  g_h1);
    cudaGetSymbolAddress((void**)&t1,  g_t1);
    cudaGetSymbolAddress((void**)&h2,  g_h2);
    cudaGetSymbolAddress((void**)&h2h, g_h2h);
    cudaGetSymbolAddress((void**)&wqT, g_wqT);
    cudaGetSymbolAddress((void**)&wkT, g_wkT);
    cudaGetSymbolAddress((void**)&wvT, g_wvT);
    cudaGetSymbolAddress((void**)&qh,  g_qh);
    cudaGetSymbolAddress((void**)&kh,  g_kh);
    cudaGetSymbolAddress((void**)&vt,  g_vt);
    cudaGetSymbolAddress((void**)&p,   g_p);
    cudaGetSymbolAddress((void**)&ph,  g_ph);
    cudaGetSymbolAddress((void**)&agg, g_agg);
    cudaGetSymbolAddress((void**)&t2,  g_t2);
    cudaGetSymbolAddress((void**)&t3,  g_t3);
    cudaGetSymbolAddress((void**)&h4,  g_h4);

    constexpr int SM_SQ = smem_bytes<64, 64>();
    cudaFuncSetAttribute(gemm_tc<64, 64, 32, 32, 1, true>,
        cudaFuncAttributeMaxDynamicSharedMemorySize, SM_SQ);
    cudaFuncSetAttribute(gemm_tc<64, 64, 32, 32, 2, true>,
        cudaFuncAttributeMaxDynamicSharedMemorySize, SM_SQ);
    cudaFuncSetAttribute(gemm_tc<64, 64, 32, 32, 0, false>,
        cudaFuncAttributeMaxDynamicSharedMemorySize, SM_SQ);
    cudaFuncSetAttribute(gemm_f16<0>, cudaFuncAttributeMaxDynamicSharedMemorySize, SMEM_F16);
    cudaFuncSetAttribute(gemm_f16<1>, cudaFuncAttributeMaxDynamicSharedMemorySize, SMEM_F16);
    cudaFuncSetAttribute(gemm_f16<2>, cudaFuncAttributeMaxDynamicSharedMemorySize, SMEM_F16);
    cudaFuncSetAttribute(gemm_f16<3>, cudaFuncAttributeMaxDynamicSharedMemorySize, SMEM_F16);

    const dim3 blk(128);
    const dim3 blk256(256);
    const dim3 gSq(DD_ / 64, NN_ / 64);              // (4, 64)
    const dim3 gOut(OUTD_ / 64, NN_ / 64);           // (2, 64)
    const dim3 gQkv(QKVD_ / 128, NN_ / 128);         // (8, 32)
    const dim3 gScore(NN_ / 128, NN_ / 128, HH_);    // (32, 32, 4)
    const dim3 gPV(DHH_ / 128, NN_ / 128, HH_);      // (2, 32, 4)

    // 0) transpose+convert attention weights to f16 [n][k]
    convT_k<<<QKVD_ * DD_ / 256, blk256>>>(wq, wqT, DD_, QKVD_);
    convT_k<<<QKVD_ * DD_ / 256, blk256>>>(wk, wkT, DD_, QKVD_);
    convT_k<<<QKVD_ * DD_ / 256, blk256>>>(wv, wvT, DD_, QKVD_);

    // 1) h1 = elu(x @ w_in + b_in + x)
    gemm_tc<64, 64, 32, 32, 1, true><<<gSq, blk, SM_SQ>>>(x, DD_,
        w_in, DD_, b_in, x, DD_, h1, DD_, DD_, 1.f);

    // 2) t1 = relu(h1 @ w_m1 + b_m1 + h1);  h2 = LN(t1) (f32 + f16)
    gemm_tc<64, 64, 32, 32, 2, true><<<gSq, blk, SM_SQ>>>(h1, DD_,
        w_m1, DD_, b_m1, h1, DD_, t1, DD_, DD_, 1.f);
    ln_k<<<NN_, blk256>>>(t1, g_m1, be_m1, h2, h2h);

    // 3) q/k projections (f16 out), v projection (f16 transposed per head)
    gemm_f16<1><<<gQkv, blk, SMEM_F16>>>(h2h, DD_, 0, wqT, DD_, 0,
        bq, qh, QKVD_, 0, DD_, 1.f);
    gemm_f16<1><<<gQkv, blk, SMEM_F16>>>(h2h, DD_, 0, wkT, DD_, 0,
        bk, kh, QKVD_, 0, DD_, 1.f);
    gemm_f16<2><<<gQkv, blk, SMEM_F16>>>(h2h, DD_, 0, wvT, DD_, 0,
        bv, vt, NN_, 0, DD_, 1.f);

    // 4) scores: p[h] = f16((1/16) * Q_h @ K_h^T)
    gemm_f16<3><<<gScore, blk, SMEM_F16>>>(qh, QKVD_, DHH_, kh, QKVD_, DHH_,
        nullptr, p, NN_, (long)NN_ * NN_, DHH_, 1.f / 16.f);

    // 5) softmax in place on f16
    softmax_h<<<HH_ * NN_, blk256>>>(p);

    // 6) agg = h2 @ wskip + bskip  (tf32)
    gemm_tc<64, 64, 32, 32, 0, false><<<gSq, blk, SM_SQ>>>(h2, DD_,
        wskip, DD_, bskip, nullptr, 0, agg, DD_, DD_, 1.f);

    // 7) per-head PV (alpha=0.25), f32 out into ph[h][n][256]
    gemm_f16<0><<<gPV, blk, SMEM_F16>>>(p, NN_, (long)NN_ * NN_,
        vt, NN_, (long)DHH_ * NN_,
        nullptr, ph, DHH_, (long)NN_ * DHH_, NN_, 0.25f);

    // 8) t2 = LN(agg + sum_h ph)
    ln_agg_k<<<NN_, blk256>>>(agg, ph, g_n1, be_n1, t2);

    // 9) t3 = relu(t2 @ w_m2 + b_m2 + t2);  h4 = LN(t3)
    gemm_tc<64, 64, 32, 32, 2, true><<<gSq, blk, SM_SQ>>>(t2, DD_,
        w_m2, DD_, b_m2, t2, DD_, t3, DD_, DD_, 1.f);
    ln_k<<<NN_, blk256>>>(t3, g_m2, be_m2, h4, nullptr);

    // 10) out = h4 @ w_mean + b_mean
    gemm_tc<64, 64, 32, 32, 0, false><<<gOut, blk, SM_SQ>>>(h4, DD_,
        w_mean, OUTD_, b_mean, nullptr, 0, out, OUTD_, DD_, 1.f);
}